// round 4
// baseline (speedup 1.0000x reference)
#include <cuda_runtime.h>
#include <cuda_bf16.h>
#include <math.h>

// ---------------------------------------------------------------------------
// Problem constants
// ---------------------------------------------------------------------------
#define BB 4
#define TT 2048
#define EE 128
#define HH 8
#define DD 1024
#define FF 4096

// ---------------------------------------------------------------------------
// Scratch (static device globals; no allocation anywhere)
// ---------------------------------------------------------------------------
__device__ float g_Xn[(size_t)BB * TT * EE];
__device__ float g_q [(size_t)BB * HH * TT * EE];
__device__ float g_k [(size_t)BB * HH * TT * EE];
__device__ float g_v [(size_t)BB * HH * TT * EE];
__device__ float g_S [(size_t)BB * HH * TT * TT];            // 512 MB
__device__ float g_cc[(size_t)BB * TT * DD];
__device__ float g_mid[(size_t)BB * TT * FF];

// ---------------------------------------------------------------------------
// Per-batch (blockIdx.z) offset helper: off(z) = (z/dv)*sd + (z%md)*sm
// ---------------------------------------------------------------------------
struct ZOff { int dv; int md; long sd; long sm; };
__device__ __forceinline__ long zoff(ZOff o, int z) {
    return (long)(z / o.dv) * o.sd + (long)(z % o.md) * o.sm;
}

// ---------------------------------------------------------------------------
// Generic tiled GEMM: C[M,N] = act( scale * A[M,K] @ B + bias )
//   BT    : B stored [N,K] (compute A @ B^T)
//   EPI   : 0 none, 1 +bias[n], 2 +bias[n] then exact GELU
//   CMODE : 0 normal; 1 skip blocks strictly above diagonal (scores);
//           2 truncate K-loop at m0+64 (attn @ v, causal attn)
// Tile 64x64, K-chunk 16, 256 threads, 4x4 per thread, software-pipelined
// global loads. M,N multiples of 64; K multiple of 16 (true for all calls).
// ---------------------------------------------------------------------------
template <int EPI, bool BT, int CMODE>
__global__ __launch_bounds__(256, 2) void gemm64(
    const float* __restrict__ A, const float* __restrict__ B,
    float* __restrict__ C, const float* __restrict__ bias,
    int M, int N, int K, int lda, int ldb, int ldc, float scale,
    ZOff oa, ZOff ob, ZOff oc, ZOff obias)
{
    const int z = blockIdx.z;
    A += zoff(oa, z);
    B += zoff(ob, z);
    C += zoff(oc, z);
    if (EPI >= 1) bias += zoff(obias, z);

    const int n0 = blockIdx.x * 64;
    const int m0 = blockIdx.y * 64;
    if (CMODE == 1 && m0 < n0) return;       // fully-masked score block
    int kEnd = K;
    if (CMODE == 2) kEnd = min(K, m0 + 64);  // causal attn cols are zero beyond

    __shared__ float As[16][68];
    __shared__ float Bs[16][68];

    const int tid = threadIdx.x;
    const int tx = tid & 15;
    const int ty = tid >> 4;

    float acc[4][4] = {};

    // A load mapping: 64 rows x 16 cols, one float4 per thread
    const int ar = tid >> 2;          // m within tile
    const int ac = (tid & 3) * 4;     // k within chunk
    const float* Ag = A + (size_t)(m0 + ar) * lda + ac;

    // B load mapping
    int br, bc;
    const float* Bg;
    if (BT) { br = tid >> 2; bc = (tid & 3) * 4;  Bg = B + (size_t)(n0 + br) * ldb + bc; }
    else    { br = tid >> 4; bc = (tid & 15) * 4; Bg = B + (size_t)br * ldb + n0 + bc; }

    // Prefetch first chunk
    float4 av = *(const float4*)(Ag);
    float4 bv = BT ? *(const float4*)(Bg) : *(const float4*)(Bg);

    for (int k0 = 0; k0 < kEnd; k0 += 16) {
        __syncthreads();
        As[ac + 0][ar] = av.x; As[ac + 1][ar] = av.y;
        As[ac + 2][ar] = av.z; As[ac + 3][ar] = av.w;
        if (BT) {
            Bs[bc + 0][br] = bv.x; Bs[bc + 1][br] = bv.y;
            Bs[bc + 2][br] = bv.z; Bs[bc + 3][br] = bv.w;
        } else {
            *(float4*)&Bs[br][bc] = bv;
        }
        __syncthreads();

        // Prefetch next chunk while computing on this one
        const int kn = k0 + 16;
        if (kn < kEnd) {
            av = *(const float4*)(Ag + kn);
            if (BT) bv = *(const float4*)(Bg + kn);
            else    bv = *(const float4*)(Bg + (size_t)kn * ldb);
        }

#pragma unroll
        for (int kk = 0; kk < 16; kk++) {
            float4 a = *(const float4*)&As[kk][ty * 4];
            float4 b = *(const float4*)&Bs[kk][tx * 4];
            acc[0][0] += a.x * b.x; acc[0][1] += a.x * b.y;
            acc[0][2] += a.x * b.z; acc[0][3] += a.x * b.w;
            acc[1][0] += a.y * b.x; acc[1][1] += a.y * b.y;
            acc[1][2] += a.y * b.z; acc[1][3] += a.y * b.w;
            acc[2][0] += a.z * b.x; acc[2][1] += a.z * b.y;
            acc[2][2] += a.z * b.z; acc[2][3] += a.z * b.w;
            acc[3][0] += a.w * b.x; acc[3][1] += a.w * b.y;
            acc[3][2] += a.w * b.z; acc[3][3] += a.w * b.w;
        }
    }

#pragma unroll
    for (int i = 0; i < 4; i++) {
        const int m = m0 + ty * 4 + i;
        const int n = n0 + tx * 4;
        float4 r;
        float* pr = &r.x;
#pragma unroll
        for (int j = 0; j < 4; j++) {
            float vv = acc[i][j] * scale;
            if (EPI >= 1) vv += bias[n + j];
            if (EPI == 2) vv = 0.5f * vv * (1.0f + erff(vv * 0.70710678118654752f));
            pr[j] = vv;
        }
        *(float4*)&C[(size_t)m * ldc + n] = r;
    }
}

// ---------------------------------------------------------------------------
// LayerNorm over last dim D (one block per row)
// ---------------------------------------------------------------------------
__global__ void ln_kernel(const float* __restrict__ x, const float* __restrict__ g,
                          const float* __restrict__ b, float* __restrict__ y, int D)
{
    const long row = blockIdx.x;
    const float* xr = x + row * D;
    float* yr = y + row * D;

    float s = 0.f, s2 = 0.f;
    for (int i = threadIdx.x; i < D; i += blockDim.x) {
        float v = xr[i];
        s += v; s2 += v * v;
    }
#pragma unroll
    for (int o = 16; o; o >>= 1) {
        s  += __shfl_xor_sync(0xFFFFFFFFu, s,  o);
        s2 += __shfl_xor_sync(0xFFFFFFFFu, s2, o);
    }
    __shared__ float shs[8], shs2[8];
    __shared__ float mu_s, ri_s;
    const int w = threadIdx.x >> 5, l = threadIdx.x & 31;
    if (l == 0) { shs[w] = s; shs2[w] = s2; }
    __syncthreads();
    if (threadIdx.x == 0) {
        const int nw = blockDim.x >> 5;
        float ts = 0.f, ts2 = 0.f;
        for (int i = 0; i < nw; i++) { ts += shs[i]; ts2 += shs2[i]; }
        float mu  = ts / D;
        float var = ts2 / D - mu * mu;
        mu_s = mu;
        ri_s = rsqrtf(var + 1e-5f);
    }
    __syncthreads();
    const float mu = mu_s, ri = ri_s;
    for (int i = threadIdx.x; i < D; i += blockDim.x)
        yr[i] = (xr[i] - mu) * ri * g[i] + b[i];
}

// ---------------------------------------------------------------------------
// Softmax over the QUERY axis t (per column s), causal mask t>=s, in place.
// Also zero-fills the masked band inside the diagonal 64-block so the
// truncated attn@v GEMM can read attn[t][s] for any s < t_block_end.
// One thread per column s; rows read coalesced across the warp.
// ---------------------------------------------------------------------------
__global__ void col_softmax(float* __restrict__ S, int T)
{
    const int s  = blockIdx.x * blockDim.x + threadIdx.x;
    const int t0 = blockIdx.x * blockDim.x;
    float* Sb = S + (size_t)blockIdx.y * T * T;

    float m = -INFINITY, zden = 0.f;
    for (int t = t0; t < T; ++t) {
        if (t >= s) {
            float xv = Sb[(size_t)t * T + s];
            float mn = fmaxf(m, xv);
            zden = zden * __expf(m - mn) + __expf(xv - mn);
            m = mn;
        }
    }
    const float inv = 1.f / zden;

    for (int t = (s & ~63); t < s; ++t)
        Sb[(size_t)t * T + s] = 0.f;
    for (int t = s; t < T; ++t) {
        float xv = Sb[(size_t)t * T + s];
        Sb[(size_t)t * T + s] = __expf(xv - m) * inv;
    }
}

// ---------------------------------------------------------------------------
// Launch
// ---------------------------------------------------------------------------
extern "C" void kernel_launch(void* const* d_in, const int* in_sizes, int n_in,
                              void* d_out, int out_size)
{
    const float* X    = (const float*)d_in[0];
    const float* ln1g = (const float*)d_in[1];
    const float* ln1b = (const float*)d_in[2];
    const float* Wq   = (const float*)d_in[3];
    const float* bq   = (const float*)d_in[4];
    const float* Wk   = (const float*)d_in[5];
    const float* bk   = (const float*)d_in[6];
    const float* Wv   = (const float*)d_in[7];
    const float* bv   = (const float*)d_in[8];
    const float* ln2g = (const float*)d_in[9];
    const float* ln2b = (const float*)d_in[10];
    const float* W1   = (const float*)d_in[11];
    const float* b1   = (const float*)d_in[12];
    const float* W2   = (const float*)d_in[13];
    const float* b2   = (const float*)d_in[14];
    float* out = (float*)d_out;

    float *Xn, *q, *k, *v, *S, *cc, *mid;
    cudaGetSymbolAddress((void**)&Xn,  g_Xn);
    cudaGetSymbolAddress((void**)&q,   g_q);
    cudaGetSymbolAddress((void**)&k,   g_k);
    cudaGetSymbolAddress((void**)&v,   g_v);
    cudaGetSymbolAddress((void**)&S,   g_S);
    cudaGetSymbolAddress((void**)&cc,  g_cc);
    cudaGetSymbolAddress((void**)&mid, g_mid);

    const ZOff z0   = {1, 1, 0, 0};
    const ZOff oXn  = {HH, 1, (long)TT * EE, 0};            // per-batch Xn slice
    const ZOff oWh  = {1, HH, 0, (long)EE * EE};            // per-head weight
    const ZOff obh  = {1, HH, 0, (long)EE};                 // per-head bias
    const ZOff oQKV = {1, 1, (long)TT * EE, 0};             // z * T*E
    const ZOff oS   = {1, 1, (long)TT * TT, 0};             // z * T*T
    const ZOff oCC  = {HH, HH, (long)TT * DD, (long)EE};    // b*T*D + h*E

    // 1. LN1
    ln_kernel<<<BB * TT, 128>>>(X, ln1g, ln1b, Xn, EE);

    // 2. Q,K,V projections (per batch*head GEMMs, 2048x128x128 each)
    dim3 gqkv(EE / 64, TT / 64, BB * HH);
    gemm64<1, false, 0><<<gqkv, 256>>>(Xn, Wq, q, bq, TT, EE, EE, EE, EE, EE, 1.f, oXn, oWh, oQKV, obh);
    gemm64<1, false, 0><<<gqkv, 256>>>(Xn, Wk, k, bk, TT, EE, EE, EE, EE, EE, 1.f, oXn, oWh, oQKV, obh);
    gemm64<1, false, 0><<<gqkv, 256>>>(Xn, Wv, v, bv, TT, EE, EE, EE, EE, EE, 1.f, oXn, oWh, oQKV, obh);

    // 3. scores = Q @ K^T / sqrt(E)   (skip blocks strictly above diagonal)
    dim3 gsc(TT / 64, TT / 64, BB * HH);
    gemm64<0, true, 1><<<gsc, 256>>>(q, k, S, nullptr, TT, TT, EE, EE, EE, TT,
                                     0.08838834764831845f, oQKV, oQKV, oS, z0);

    // 4. softmax over query axis (per column), causal, in place
    dim3 gsm(TT / 256, BB * HH);
    col_softmax<<<gsm, 256>>>(S, TT);

    // 5. out = attn @ V  -> concat layout [B,T,H*E]  (K-loop truncated at diag)
    dim3 gav(EE / 64, TT / 64, BB * HH);
    gemm64<0, false, 2><<<gav, 256>>>(S, v, cc, nullptr, TT, EE, TT, TT, EE, DD,
                                      1.f, oS, oQKV, oCC, z0);

    // 6. LN2 (in place on concat)
    ln_kernel<<<BB * TT, 128>>>(cc, ln2g, ln2b, cc, DD);

    // 7. MLP: mid = gelu(cc @ W1 + b1)
    dim3 g1(FF / 64, (BB * TT) / 64, 1);
    gemm64<2, false, 0><<<g1, 256>>>(cc, W1, mid, b1, BB * TT, FF, DD, DD, FF, FF,
                                     1.f, z0, z0, z0, z0);

    // 8. out = mid @ W2 + b2
    dim3 g2(EE / 64, (BB * TT) / 64, 1);
    gemm64<1, false, 0><<<g2, 256>>>(mid, W2, out, b2, BB * TT, EE, FF, FF, EE, EE,
                                     1.f, z0, z0, z0, z0);
}

// round 5
// speedup vs baseline: 1.2661x; 1.2661x over previous
#include <cuda_runtime.h>
#include <cuda_bf16.h>
#include <math.h>
#include <stdint.h>

// ---------------------------------------------------------------------------
// Problem constants
// ---------------------------------------------------------------------------
#define BB 4
#define TT 2048
#define EE 128
#define HH 8
#define DD 1024
#define FF 4096

// ---------------------------------------------------------------------------
// Scratch (static device globals; no allocation anywhere)
// ---------------------------------------------------------------------------
__device__ float g_Xn[(size_t)BB * TT * EE];
__device__ float g_q [(size_t)BB * HH * TT * EE];
__device__ float g_k [(size_t)BB * HH * TT * EE];
__device__ float g_v [(size_t)BB * HH * TT * EE];
__device__ float g_S [(size_t)BB * HH * TT * TT];            // 512 MB
__device__ float g_cc[(size_t)BB * TT * DD];
__device__ float g_mid[(size_t)BB * TT * FF];

// ---------------------------------------------------------------------------
// Per-batch (blockIdx.z) offset helper
// ---------------------------------------------------------------------------
struct ZOff { int dv; int md; long sd; long sm; };
__device__ __forceinline__ long zoff(ZOff o, int z) {
    return (long)(z / o.dv) * o.sd + (long)(z % o.md) * o.sm;
}

// bf16 split helpers
__device__ __forceinline__ void split_bf16(float x, __nv_bfloat16& h, __nv_bfloat16& l) {
    h = __float2bfloat16(x);
    l = __float2bfloat16(x - __bfloat162float(h));
}
__device__ __forceinline__ uint32_t pack2(__nv_bfloat16 a, __nv_bfloat16 b) {
    // low 16 bits = a (even k), high 16 = b (odd k)
    uint32_t ua = __bfloat16_as_ushort(a), ub = __bfloat16_as_ushort(b);
    return ua | (ub << 16);
}

__device__ __forceinline__ void mma_bf16(float& c0, float& c1, float& c2, float& c3,
                                         uint32_t a0, uint32_t a1, uint32_t a2, uint32_t a3,
                                         uint32_t b0, uint32_t b1) {
    asm volatile(
        "mma.sync.aligned.m16n8k16.row.col.f32.bf16.bf16.f32 "
        "{%0,%1,%2,%3}, {%4,%5,%6,%7}, {%8,%9}, {%0,%1,%2,%3};"
        : "+f"(c0), "+f"(c1), "+f"(c2), "+f"(c3)
        : "r"(a0), "r"(a1), "r"(a2), "r"(a3), "r"(b0), "r"(b1));
}

// ---------------------------------------------------------------------------
// Tensor-core GEMM via mma.sync bf16 with hi/lo split (fp32-grade accuracy).
// C[M,N] = act( scale * A[M,K] @ B + bias )
//   BT    : B stored [N,K] (compute A @ B^T)
//   EPI   : 0 none, 1 +bias[n], 2 +bias[n] then exact GELU
//   CMODE : 0 normal; 1 skip blocks strictly above diagonal (scores);
//           2 truncate K-loop at m0+128 (attn @ v, causal attn)
// Block tile 128x128, BK=32, 256 threads (8 warps, each 32m x 64n).
// M,N multiples of 128; K multiple of 32. All calls satisfy this.
// ---------------------------------------------------------------------------
template <int EPI, bool BT, int CMODE>
__global__ __launch_bounds__(256) void gemm_mma(
    const float* __restrict__ A, const float* __restrict__ B,
    float* __restrict__ C, const float* __restrict__ bias,
    int M, int N, int K, int lda, int ldb, int ldc, float scale,
    ZOff oa, ZOff ob, ZOff oc, ZOff obias)
{
    const int z = blockIdx.z;
    A += zoff(oa, z);
    B += zoff(ob, z);
    C += zoff(oc, z);
    if (EPI >= 1) bias += zoff(obias, z);

    const int n0 = blockIdx.x * 128;
    const int m0 = blockIdx.y * 128;
    if (CMODE == 1 && m0 < n0) return;
    int kEnd = K;
    if (CMODE == 2) kEnd = min(K, m0 + 128);

    // SMEM: A as halves [m][k] (pad 8 -> conflict-free frag loads),
    //       B as k-paired words [k/2][n] (pad 8).
    __shared__ __nv_bfloat16 Ah[128][40], Al[128][40];
    __shared__ uint32_t Bh[16][136], Bl[16][136];

    const int tid  = threadIdx.x;
    const int lane = tid & 31;
    const int wid  = tid >> 5;
    const int wm   = wid & 3;      // 4 m-slices of 32
    const int wn   = wid >> 2;     // 2 n-slices of 64

    float acc[2][8][4];
#pragma unroll
    for (int i = 0; i < 2; i++)
#pragma unroll
        for (int j = 0; j < 8; j++)
#pragma unroll
            for (int r = 0; r < 4; r++) acc[i][j][r] = 0.f;

    // ---- global load mappings ----
    // A: 128 rows x 32 cols per chunk. thread: row ar+32*i, cols ac..ac+3
    const int ar = tid >> 3;           // 0..31
    const int ac = (tid & 7) * 4;      // 0..28
    const float* Ag = A + (size_t)(m0 + ar) * lda + ac;

    // B (!BT): [K][N]: thread covers k rows kb,kb+1, cols nb..nb+7
    // B (BT) : [N][K]: thread covers row n=tid>>1, k range kh..kh+15
    const int kb = (tid >> 4) * 2;     // 0..30
    const int nb = (tid & 15) * 8;     // 0..120
    const int bn_row = tid >> 1;       // 0..127
    const int kh = (tid & 1) * 16;     // 0,16
    const float* Bg;
    if (BT) Bg = B + (size_t)(n0 + bn_row) * ldb + kh;
    else    Bg = B + (size_t)kb * ldb + n0 + nb;

    // ---- prefetch first chunk ----
    float4 av[4];
    float4 bv[4];
#pragma unroll
    for (int i = 0; i < 4; i++) av[i] = *(const float4*)(Ag + (size_t)(32 * i) * lda);
    if (BT) {
#pragma unroll
        for (int i = 0; i < 4; i++) bv[i] = *(const float4*)(Bg + 4 * i);
    } else {
        bv[0] = *(const float4*)(Bg);
        bv[1] = *(const float4*)(Bg + 4);
        bv[2] = *(const float4*)(Bg + ldb);
        bv[3] = *(const float4*)(Bg + ldb + 4);
    }

    for (int k0 = 0; k0 < kEnd; k0 += 32) {
        __syncthreads();
        // ---- store A (hi/lo) ----
#pragma unroll
        for (int i = 0; i < 4; i++) {
            const float* f = &av[i].x;
            int r = ar + 32 * i;
#pragma unroll
            for (int j = 0; j < 4; j++) {
                __nv_bfloat16 h, l;
                split_bf16(f[j], h, l);
                Ah[r][ac + j] = h;
                Al[r][ac + j] = l;
            }
        }
        // ---- store B (k-paired, hi/lo) ----
        if (BT) {
            const float* f = &bv[0].x;   // 16 consecutive k of row bn_row
#pragma unroll
            for (int j = 0; j < 8; j++) {
                __nv_bfloat16 h0, l0, h1, l1;
                split_bf16(f[2 * j], h0, l0);
                split_bf16(f[2 * j + 1], h1, l1);
                Bh[(kh >> 1) + j][bn_row] = pack2(h0, h1);
                Bl[(kh >> 1) + j][bn_row] = pack2(l0, l1);
            }
        } else {
            const float* r0 = &bv[0].x;  // row kb, 8 cols
            const float* r1 = &bv[2].x;  // row kb+1
#pragma unroll
            for (int j = 0; j < 8; j++) {
                __nv_bfloat16 h0, l0, h1, l1;
                split_bf16(r0[j], h0, l0);
                split_bf16(r1[j], h1, l1);
                Bh[kb >> 1][nb + j] = pack2(h0, h1);
                Bl[kb >> 1][nb + j] = pack2(l0, l1);
            }
        }
        __syncthreads();

        // ---- prefetch next chunk ----
        const int kn = k0 + 32;
        if (kn < kEnd) {
#pragma unroll
            for (int i = 0; i < 4; i++) av[i] = *(const float4*)(Ag + (size_t)(32 * i) * lda + kn);
            if (BT) {
#pragma unroll
                for (int i = 0; i < 4; i++) bv[i] = *(const float4*)(Bg + kn + 4 * i);
            } else {
                bv[0] = *(const float4*)(Bg + (size_t)kn * ldb);
                bv[1] = *(const float4*)(Bg + (size_t)kn * ldb + 4);
                bv[2] = *(const float4*)(Bg + (size_t)(kn + 1) * ldb);
                bv[3] = *(const float4*)(Bg + (size_t)(kn + 1) * ldb + 4);
            }
        }

        // ---- MMA: 2 k-steps of 16 ----
#pragma unroll
        for (int s = 0; s < 2; s++) {
            const int kk = s * 16;
            uint32_t ah[2][4], al[2][4];
#pragma unroll
            for (int mt = 0; mt < 2; mt++) {
                const int am = wm * 32 + mt * 16 + (lane >> 2);
                const int acol = kk + (lane & 3) * 2;
                ah[mt][0] = *(const uint32_t*)&Ah[am][acol];
                ah[mt][1] = *(const uint32_t*)&Ah[am + 8][acol];
                ah[mt][2] = *(const uint32_t*)&Ah[am][acol + 8];
                ah[mt][3] = *(const uint32_t*)&Ah[am + 8][acol + 8];
                al[mt][0] = *(const uint32_t*)&Al[am][acol];
                al[mt][1] = *(const uint32_t*)&Al[am + 8][acol];
                al[mt][2] = *(const uint32_t*)&Al[am][acol + 8];
                al[mt][3] = *(const uint32_t*)&Al[am + 8][acol + 8];
            }
#pragma unroll
            for (int nt = 0; nt < 8; nt++) {
                const int bcol = wn * 64 + nt * 8 + (lane >> 2);
                const int brow = (kk >> 1) + (lane & 3);
                uint32_t bh0 = Bh[brow][bcol];
                uint32_t bh1 = Bh[brow + 4][bcol];
                uint32_t bl0 = Bl[brow][bcol];
                uint32_t bl1 = Bl[brow + 4][bcol];
#pragma unroll
                for (int mt = 0; mt < 2; mt++) {
                    float* c = acc[mt][nt];
                    mma_bf16(c[0], c[1], c[2], c[3],
                             ah[mt][0], ah[mt][1], ah[mt][2], ah[mt][3], bh0, bh1);
                    mma_bf16(c[0], c[1], c[2], c[3],
                             ah[mt][0], ah[mt][1], ah[mt][2], ah[mt][3], bl0, bl1);
                    mma_bf16(c[0], c[1], c[2], c[3],
                             al[mt][0], al[mt][1], al[mt][2], al[mt][3], bh0, bh1);
                }
            }
        }
    }

    // ---- epilogue ----
#pragma unroll
    for (int mt = 0; mt < 2; mt++) {
#pragma unroll
        for (int nt = 0; nt < 8; nt++) {
            const int r0 = m0 + wm * 32 + mt * 16 + (lane >> 2);
            const int cb = n0 + wn * 64 + nt * 8 + (lane & 3) * 2;
            float v[4];
#pragma unroll
            for (int r = 0; r < 4; r++) v[r] = acc[mt][nt][r] * scale;
            if (EPI >= 1) {
                float b0 = bias[cb], b1 = bias[cb + 1];
                v[0] += b0; v[1] += b1; v[2] += b0; v[3] += b1;
            }
            if (EPI == 2) {
#pragma unroll
                for (int r = 0; r < 4; r++)
                    v[r] = 0.5f * v[r] * (1.0f + erff(v[r] * 0.70710678118654752f));
            }
            *(float2*)&C[(size_t)r0 * ldc + cb]       = make_float2(v[0], v[1]);
            *(float2*)&C[(size_t)(r0 + 8) * ldc + cb] = make_float2(v[2], v[3]);
        }
    }
}

// ---------------------------------------------------------------------------
// LayerNorm over last dim D (one block per row)
// ---------------------------------------------------------------------------
__global__ void ln_kernel(const float* __restrict__ x, const float* __restrict__ g,
                          const float* __restrict__ b, float* __restrict__ y, int D)
{
    const long row = blockIdx.x;
    const float* xr = x + row * D;
    float* yr = y + row * D;

    float s = 0.f, s2 = 0.f;
    for (int i = threadIdx.x; i < D; i += blockDim.x) {
        float v = xr[i];
        s += v; s2 += v * v;
    }
#pragma unroll
    for (int o = 16; o; o >>= 1) {
        s  += __shfl_xor_sync(0xFFFFFFFFu, s,  o);
        s2 += __shfl_xor_sync(0xFFFFFFFFu, s2, o);
    }
    __shared__ float shs[8], shs2[8];
    __shared__ float mu_s, ri_s;
    const int w = threadIdx.x >> 5, l = threadIdx.x & 31;
    if (l == 0) { shs[w] = s; shs2[w] = s2; }
    __syncthreads();
    if (threadIdx.x == 0) {
        const int nw = blockDim.x >> 5;
        float ts = 0.f, ts2 = 0.f;
        for (int i = 0; i < nw; i++) { ts += shs[i]; ts2 += shs2[i]; }
        float mu  = ts / D;
        float var = ts2 / D - mu * mu;
        mu_s = mu;
        ri_s = rsqrtf(var + 1e-5f);
    }
    __syncthreads();
    const float mu = mu_s, ri = ri_s;
    for (int i = threadIdx.x; i < D; i += blockDim.x)
        yr[i] = (xr[i] - mu) * ri * g[i] + b[i];
}

// ---------------------------------------------------------------------------
// Softmax over the QUERY axis t (per column s), causal t>=s, in place.
// Zero-fills the masked band inside the diagonal 128-block (the attn@v GEMM
// truncates its K loop at m0+128 and reads those entries).
// ---------------------------------------------------------------------------
__global__ void col_softmax(float* __restrict__ S, int T)
{
    const int s  = blockIdx.x * blockDim.x + threadIdx.x;
    const int t0 = blockIdx.x * blockDim.x;
    float* Sb = S + (size_t)blockIdx.y * T * T;

    float m = -INFINITY, zden = 0.f;
    for (int t = t0; t < T; ++t) {
        if (t >= s) {
            float xv = Sb[(size_t)t * T + s];
            float mn = fmaxf(m, xv);
            zden = zden * __expf(m - mn) + __expf(xv - mn);
            m = mn;
        }
    }
    const float inv = 1.f / zden;

    for (int t = (s & ~127); t < s; ++t)
        Sb[(size_t)t * T + s] = 0.f;
    for (int t = s; t < T; ++t) {
        float xv = Sb[(size_t)t * T + s];
        Sb[(size_t)t * T + s] = __expf(xv - m) * inv;
    }
}

// ---------------------------------------------------------------------------
// Launch
// ---------------------------------------------------------------------------
extern "C" void kernel_launch(void* const* d_in, const int* in_sizes, int n_in,
                              void* d_out, int out_size)
{
    const float* X    = (const float*)d_in[0];
    const float* ln1g = (const float*)d_in[1];
    const float* ln1b = (const float*)d_in[2];
    const float* Wq   = (const float*)d_in[3];
    const float* bq   = (const float*)d_in[4];
    const float* Wk   = (const float*)d_in[5];
    const float* bk   = (const float*)d_in[6];
    const float* Wv   = (const float*)d_in[7];
    const float* bv   = (const float*)d_in[8];
    const float* ln2g = (const float*)d_in[9];
    const float* ln2b = (const float*)d_in[10];
    const float* W1   = (const float*)d_in[11];
    const float* b1   = (const float*)d_in[12];
    const float* W2   = (const float*)d_in[13];
    const float* b2   = (const float*)d_in[14];
    float* out = (float*)d_out;

    float *Xn, *q, *k, *v, *S, *cc, *mid;
    cudaGetSymbolAddress((void**)&Xn,  g_Xn);
    cudaGetSymbolAddress((void**)&q,   g_q);
    cudaGetSymbolAddress((void**)&k,   g_k);
    cudaGetSymbolAddress((void**)&v,   g_v);
    cudaGetSymbolAddress((void**)&S,   g_S);
    cudaGetSymbolAddress((void**)&cc,  g_cc);
    cudaGetSymbolAddress((void**)&mid, g_mid);

    const ZOff z0   = {1, 1, 0, 0};
    const ZOff oXn  = {HH, 1, (long)TT * EE, 0};
    const ZOff oWh  = {1, HH, 0, (long)EE * EE};
    const ZOff obh  = {1, HH, 0, (long)EE};
    const ZOff oQKV = {1, 1, (long)TT * EE, 0};
    const ZOff oS   = {1, 1, (long)TT * TT, 0};
    const ZOff oCC  = {HH, HH, (long)TT * DD, (long)EE};

    // 1. LN1
    ln_kernel<<<BB * TT, 128>>>(X, ln1g, ln1b, Xn, EE);

    // 2. Q,K,V projections
    dim3 gqkv(EE / 128, TT / 128, BB * HH);
    gemm_mma<1, false, 0><<<gqkv, 256>>>(Xn, Wq, q, bq, TT, EE, EE, EE, EE, EE, 1.f, oXn, oWh, oQKV, obh);
    gemm_mma<1, false, 0><<<gqkv, 256>>>(Xn, Wk, k, bk, TT, EE, EE, EE, EE, EE, 1.f, oXn, oWh, oQKV, obh);
    gemm_mma<1, false, 0><<<gqkv, 256>>>(Xn, Wv, v, bv, TT, EE, EE, EE, EE, EE, 1.f, oXn, oWh, oQKV, obh);

    // 3. scores = Q @ K^T / sqrt(E)
    dim3 gsc(TT / 128, TT / 128, BB * HH);
    gemm_mma<0, true, 1><<<gsc, 256>>>(q, k, S, nullptr, TT, TT, EE, EE, EE, TT,
                                       0.08838834764831845f, oQKV, oQKV, oS, z0);

    // 4. column softmax (query axis), causal, in place
    dim3 gsm(TT / 256, BB * HH);
    col_softmax<<<gsm, 256>>>(S, TT);

    // 5. out = attn @ V -> concat [B,T,H*E]
    dim3 gav(EE / 128, TT / 128, BB * HH);
    gemm_mma<0, false, 2><<<gav, 256>>>(S, v, cc, nullptr, TT, EE, TT, TT, EE, DD,
                                        1.f, oS, oQKV, oCC, z0);

    // 6. LN2
    ln_kernel<<<BB * TT, 128>>>(cc, ln2g, ln2b, cc, DD);

    // 7. MLP: mid = gelu(cc @ W1 + b1)
    dim3 g1(FF / 128, (BB * TT) / 128, 1);
    gemm_mma<2, false, 0><<<g1, 256>>>(cc, W1, mid, b1, BB * TT, FF, DD, DD, FF, FF,
                                       1.f, z0, z0, z0, z0);

    // 8. out = mid @ W2 + b2
    dim3 g2(EE / 128, (BB * TT) / 128, 1);
    gemm_mma<1, false, 0><<<g2, 256>>>(mid, W2, out, b2, BB * TT, EE, FF, FF, EE, EE,
                                       1.f, z0, z0, z0, z0);
}

// round 6
// speedup vs baseline: 1.6153x; 1.2758x over previous
#include <cuda_runtime.h>
#include <cuda_bf16.h>
#include <math.h>
#include <stdint.h>

#define BB 4
#define TT 2048
#define EE 128
#define HH 8
#define DD 1024
#define FF 4096

typedef __nv_bfloat16 bf16;

// ---------------------------------------------------------------------------
// Scratch (static device globals; no allocation anywhere)
// ---------------------------------------------------------------------------
__device__ float g_S  [(size_t)BB*HH*TT*TT];          // 512 MB f32 scores
__device__ bf16  g_Sh [(size_t)BB*HH*TT*TT];          // attn hi plane
__device__ bf16  g_Sl [(size_t)BB*HH*TT*TT];          // attn lo plane
__device__ bf16  g_Xnh[(size_t)BB*TT*EE], g_Xnl[(size_t)BB*TT*EE];
__device__ bf16  g_qh [(size_t)BB*HH*TT*EE], g_ql [(size_t)BB*HH*TT*EE];
__device__ bf16  g_kh [(size_t)BB*HH*TT*EE], g_kl [(size_t)BB*HH*TT*EE];
__device__ bf16  g_vh [(size_t)BB*HH*TT*EE], g_vl [(size_t)BB*HH*TT*EE];
__device__ bf16  g_vth[(size_t)BB*HH*TT*EE], g_vtl[(size_t)BB*HH*TT*EE];
__device__ float g_cc [(size_t)BB*TT*DD];
__device__ bf16  g_cch[(size_t)BB*TT*DD], g_ccl[(size_t)BB*TT*DD];
__device__ bf16  g_midh[(size_t)BB*TT*FF], g_midl[(size_t)BB*TT*FF];
__device__ bf16  g_Wqh[(size_t)HH*EE*EE], g_Wql[(size_t)HH*EE*EE];
__device__ bf16  g_Wkh[(size_t)HH*EE*EE], g_Wkl[(size_t)HH*EE*EE];
__device__ bf16  g_Wvh[(size_t)HH*EE*EE], g_Wvl[(size_t)HH*EE*EE];
__device__ bf16  g_W1h[(size_t)DD*FF],   g_W1l[(size_t)DD*FF];   // [F][D]
__device__ bf16  g_W2h[(size_t)FF*EE],   g_W2l[(size_t)FF*EE];   // [E][F]
__device__ float g_part[(size_t)4*BB*TT*EE];                      // split-K partials

// ---------------------------------------------------------------------------
struct ZOff { int dv; int md; long sd; long sm; };
__device__ __forceinline__ long zoff(ZOff o, int z) {
    return (long)(z / o.dv) * o.sd + (long)(z % o.md) * o.sm;
}

__device__ __forceinline__ void split_bf16(float x, bf16& h, bf16& l) {
    h = __float2bfloat16(x);
    l = __float2bfloat16(x - __bfloat162float(h));
}
__device__ __forceinline__ uint32_t pack2(bf16 a, bf16 b) {
    uint32_t ua = __bfloat16_as_ushort(a), ub = __bfloat16_as_ushort(b);
    return ua | (ub << 16);
}

__device__ __forceinline__ void mma_bf16(float& c0, float& c1, float& c2, float& c3,
                                         uint32_t a0, uint32_t a1, uint32_t a2, uint32_t a3,
                                         uint32_t b0, uint32_t b1) {
    asm volatile(
        "mma.sync.aligned.m16n8k16.row.col.f32.bf16.bf16.f32 "
        "{%0,%1,%2,%3}, {%4,%5,%6,%7}, {%8,%9}, {%0,%1,%2,%3};"
        : "+f"(c0), "+f"(c1), "+f"(c2), "+f"(c3)
        : "r"(a0), "r"(a1), "r"(a2), "r"(a3), "r"(b0), "r"(b1));
}

__device__ __forceinline__ void cpa16(void* smem, const void* gmem) {
    uint32_t s = (uint32_t)__cvta_generic_to_shared(smem);
    asm volatile("cp.async.cg.shared.global [%0], [%1], 16;" :: "r"(s), "l"(gmem));
}
__device__ __forceinline__ void cpa_commit_wait() {
    asm volatile("cp.async.commit_group;");
    asm volatile("cp.async.wait_group 0;" ::: "memory");
}

// ---------------------------------------------------------------------------
// GEMM on pre-split bf16 hi/lo planes. C = act(scale * A @ B^T + bias)
// A: [M][K] planes (lda), B: [N][K] planes (ldb).
//   EPI   : 0 f32*scale -> Cf ; 1 split+bias -> Ch/Cl ; 2 split+bias+gelu -> Ch/Cl
//   CMODE : 0 normal; 1 skip blocks strictly above diagonal;
//           2 truncate K-loop at m0+128 (attn @ v)
// Block tile 128x128, BK=32, 256 threads (8 warps 32m x 64n). cp.async loads.
// ---------------------------------------------------------------------------
template <int EPI, int CMODE>
__global__ __launch_bounds__(256, 2) void gemm_bt(
    const bf16* __restrict__ Ahg, const bf16* __restrict__ Alg,
    const bf16* __restrict__ Bhg, const bf16* __restrict__ Blg,
    float* __restrict__ Cf, bf16* __restrict__ Chg, bf16* __restrict__ Clg,
    const float* __restrict__ bias,
    int M, int N, int K, int lda, int ldb, int ldc, float scale,
    ZOff oa, ZOff ob, ZOff oc, ZOff obias)
{
    const int z = blockIdx.z;
    const long za = zoff(oa, z), zb = zoff(ob, z), zc = zoff(oc, z);
    Ahg += za; Alg += za;
    Bhg += zb; Blg += zb;
    if (EPI == 0) Cf += zc; else { Chg += zc; Clg += zc; }
    if (EPI >= 1) bias += zoff(obias, z);

    const int n0 = blockIdx.x * 128;
    const int m0 = blockIdx.y * 128;
    if (CMODE == 1 && m0 < n0) return;
    int kEnd = K;
    if (CMODE == 2) kEnd = min(K, m0 + 128);

    __shared__ bf16 Ah[128][40], Al[128][40], Bh[128][40], Bl[128][40];

    const int tid  = threadIdx.x;
    const int lane = tid & 31;
    const int wid  = tid >> 5;
    const int wm   = wid & 3;
    const int wn   = wid >> 2;

    float acc[2][8][4];
#pragma unroll
    for (int i = 0; i < 2; i++)
#pragma unroll
        for (int j = 0; j < 8; j++)
#pragma unroll
            for (int r = 0; r < 4; r++) acc[i][j][r] = 0.f;

    // loaders: thread covers row lr, k-cols [lc, lc+16)
    const int lr = tid >> 1;
    const int lc = (tid & 1) * 16;
    const bf16* Agh = Ahg + (size_t)(m0 + lr) * lda + lc;
    const bf16* Agl = Alg + (size_t)(m0 + lr) * lda + lc;
    const bf16* Bgh = Bhg + (size_t)(n0 + lr) * ldb + lc;
    const bf16* Bgl = Blg + (size_t)(n0 + lr) * ldb + lc;

    for (int k0 = 0; k0 < kEnd; k0 += 32) {
        __syncthreads();
        cpa16(&Ah[lr][lc], Agh + k0); cpa16(&Ah[lr][lc + 8], Agh + k0 + 8);
        cpa16(&Al[lr][lc], Agl + k0); cpa16(&Al[lr][lc + 8], Agl + k0 + 8);
        cpa16(&Bh[lr][lc], Bgh + k0); cpa16(&Bh[lr][lc + 8], Bgh + k0 + 8);
        cpa16(&Bl[lr][lc], Bgl + k0); cpa16(&Bl[lr][lc + 8], Bgl + k0 + 8);
        cpa_commit_wait();
        __syncthreads();

#pragma unroll
        for (int s = 0; s < 2; s++) {
            const int kk = s * 16;
            uint32_t ah[2][4], al[2][4];
#pragma unroll
            for (int mt = 0; mt < 2; mt++) {
                const int am = wm * 32 + mt * 16 + (lane >> 2);
                const int acol = kk + (lane & 3) * 2;
                ah[mt][0] = *(const uint32_t*)&Ah[am][acol];
                ah[mt][1] = *(const uint32_t*)&Ah[am + 8][acol];
                ah[mt][2] = *(const uint32_t*)&Ah[am][acol + 8];
                ah[mt][3] = *(const uint32_t*)&Ah[am + 8][acol + 8];
                al[mt][0] = *(const uint32_t*)&Al[am][acol];
                al[mt][1] = *(const uint32_t*)&Al[am + 8][acol];
                al[mt][2] = *(const uint32_t*)&Al[am][acol + 8];
                al[mt][3] = *(const uint32_t*)&Al[am + 8][acol + 8];
            }
#pragma unroll
            for (int nt = 0; nt < 8; nt++) {
                const int bcol = wn * 64 + nt * 8 + (lane >> 2);
                const int kb2  = kk + (lane & 3) * 2;
                uint32_t bh0 = *(const uint32_t*)&Bh[bcol][kb2];
                uint32_t bh1 = *(const uint32_t*)&Bh[bcol][kb2 + 8];
                uint32_t bl0 = *(const uint32_t*)&Bl[bcol][kb2];
                uint32_t bl1 = *(const uint32_t*)&Bl[bcol][kb2 + 8];
#pragma unroll
                for (int mt = 0; mt < 2; mt++) {
                    float* c = acc[mt][nt];
                    mma_bf16(c[0], c[1], c[2], c[3],
                             ah[mt][0], ah[mt][1], ah[mt][2], ah[mt][3], bh0, bh1);
                    mma_bf16(c[0], c[1], c[2], c[3],
                             ah[mt][0], ah[mt][1], ah[mt][2], ah[mt][3], bl0, bl1);
                    mma_bf16(c[0], c[1], c[2], c[3],
                             al[mt][0], al[mt][1], al[mt][2], al[mt][3], bh0, bh1);
                }
            }
        }
    }

    // epilogue
#pragma unroll
    for (int mt = 0; mt < 2; mt++) {
#pragma unroll
        for (int nt = 0; nt < 8; nt++) {
            const int r0 = m0 + wm * 32 + mt * 16 + (lane >> 2);
            const int cb = n0 + wn * 64 + nt * 8 + (lane & 3) * 2;
            float v[4];
#pragma unroll
            for (int r = 0; r < 4; r++) v[r] = acc[mt][nt][r] * scale;
            if (EPI >= 1) {
                float b0 = bias[cb], b1 = bias[cb + 1];
                v[0] += b0; v[1] += b1; v[2] += b0; v[3] += b1;
            }
            if (EPI == 2) {
#pragma unroll
                for (int r = 0; r < 4; r++)
                    v[r] = 0.5f * v[r] * (1.0f + erff(v[r] * 0.70710678118654752f));
            }
            if (EPI == 0) {
                *(float2*)&Cf[(size_t)r0 * ldc + cb]       = make_float2(v[0], v[1]);
                *(float2*)&Cf[(size_t)(r0 + 8) * ldc + cb] = make_float2(v[2], v[3]);
            } else {
                bf16 h0, l0, h1, l1;
                split_bf16(v[0], h0, l0); split_bf16(v[1], h1, l1);
                *(uint32_t*)&Chg[(size_t)r0 * ldc + cb] = pack2(h0, h1);
                *(uint32_t*)&Clg[(size_t)r0 * ldc + cb] = pack2(l0, l1);
                split_bf16(v[2], h0, l0); split_bf16(v[3], h1, l1);
                *(uint32_t*)&Chg[(size_t)(r0 + 8) * ldc + cb] = pack2(h0, h1);
                *(uint32_t*)&Clg[(size_t)(r0 + 8) * ldc + cb] = pack2(l0, l1);
            }
        }
    }
}

// ---------------------------------------------------------------------------
// Split+transpose f32 [R][C] -> hi/lo bf16 planes [C][R]; z = matrix index.
// ---------------------------------------------------------------------------
__global__ void split_tr(const float* __restrict__ src, bf16* __restrict__ oh,
                         bf16* __restrict__ ol, int R, int C)
{
    __shared__ float t[32][33];
    const size_t zo = (size_t)blockIdx.z * R * C;
    const int c0 = blockIdx.x * 32, r0 = blockIdx.y * 32;
    const int tx = threadIdx.x, ty = threadIdx.y;   // 32x8
    for (int i = ty; i < 32; i += 8)
        t[i][tx] = src[zo + (size_t)(r0 + i) * C + c0 + tx];
    __syncthreads();
    for (int i = ty; i < 32; i += 8) {
        float v = t[tx][i];
        bf16 h, l; split_bf16(v, h, l);
        oh[zo + (size_t)(c0 + i) * R + r0 + tx] = h;
        ol[zo + (size_t)(c0 + i) * R + r0 + tx] = l;
    }
}

// Transpose bf16 planes [R][C] -> [C][R]; z = matrix index.
__global__ void tr_planes(const bf16* __restrict__ ih, const bf16* __restrict__ il,
                          bf16* __restrict__ oh, bf16* __restrict__ ol, int R, int C)
{
    __shared__ bf16 th[32][33], tl[32][33];
    const size_t zo = (size_t)blockIdx.z * R * C;
    const int c0 = blockIdx.x * 32, r0 = blockIdx.y * 32;
    const int tx = threadIdx.x, ty = threadIdx.y;
    for (int i = ty; i < 32; i += 8) {
        th[i][tx] = ih[zo + (size_t)(r0 + i) * C + c0 + tx];
        tl[i][tx] = il[zo + (size_t)(r0 + i) * C + c0 + tx];
    }
    __syncthreads();
    for (int i = ty; i < 32; i += 8) {
        oh[zo + (size_t)(c0 + i) * R + r0 + tx] = th[tx][i];
        ol[zo + (size_t)(c0 + i) * R + r0 + tx] = tl[tx][i];
    }
}

// ---------------------------------------------------------------------------
// LayerNorm -> hi/lo bf16 planes
// ---------------------------------------------------------------------------
__global__ void ln_split(const float* __restrict__ x, const float* __restrict__ g,
                         const float* __restrict__ b, bf16* __restrict__ yh,
                         bf16* __restrict__ yl, int D)
{
    const long row = blockIdx.x;
    const float* xr = x + row * D;

    float s = 0.f, s2 = 0.f;
    for (int i = threadIdx.x; i < D; i += blockDim.x) {
        float v = xr[i];
        s += v; s2 += v * v;
    }
#pragma unroll
    for (int o = 16; o; o >>= 1) {
        s  += __shfl_xor_sync(0xFFFFFFFFu, s,  o);
        s2 += __shfl_xor_sync(0xFFFFFFFFu, s2, o);
    }
    __shared__ float shs[8], shs2[8];
    __shared__ float mu_s, ri_s;
    const int w = threadIdx.x >> 5, l = threadIdx.x & 31;
    if (l == 0) { shs[w] = s; shs2[w] = s2; }
    __syncthreads();
    if (threadIdx.x == 0) {
        const int nw = blockDim.x >> 5;
        float ts = 0.f, ts2 = 0.f;
        for (int i = 0; i < nw; i++) { ts += shs[i]; ts2 += shs2[i]; }
        float mu  = ts / D;
        float var = ts2 / D - mu * mu;
        mu_s = mu;
        ri_s = rsqrtf(var + 1e-5f);
    }
    __syncthreads();
    const float mu = mu_s, ri = ri_s;
    for (int i = threadIdx.x; i < D; i += blockDim.x) {
        float v = (xr[i] - mu) * ri * g[i] + b[i];
        bf16 h, lo; split_bf16(v, h, lo);
        yh[row * D + i] = h;
        yl[row * D + i] = lo;
    }
}

// ---------------------------------------------------------------------------
// Column softmax (over query axis t), causal t>=s; reads f32 S, writes hi/lo
// bf16 attn planes. Zero-fills the masked band inside the diagonal 128-block.
// ---------------------------------------------------------------------------
__global__ void col_softmax(const float* __restrict__ S, bf16* __restrict__ Sh,
                            bf16* __restrict__ Sl, int T)
{
    const int s  = blockIdx.x * blockDim.x + threadIdx.x;
    const int t0 = blockIdx.x * blockDim.x;
    const size_t zo = (size_t)blockIdx.y * T * T;
    const float* Sb = S + zo;
    bf16* Shb = Sh + zo;
    bf16* Slb = Sl + zo;

    float m = -INFINITY, zden = 0.f;
    for (int t = t0; t < T; ++t) {
        if (t >= s) {
            float xv = Sb[(size_t)t * T + s];
            float mn = fmaxf(m, xv);
            zden = zden * __expf(m - mn) + __expf(xv - mn);
            m = mn;
        }
    }
    const float inv = 1.f / zden;

    const bf16 z16 = __float2bfloat16(0.f);
    for (int t = (s & ~127); t < s; ++t) {
        Shb[(size_t)t * T + s] = z16;
        Slb[(size_t)t * T + s] = z16;
    }
    for (int t = s; t < T; ++t) {
        float xv = Sb[(size_t)t * T + s];
        float v = __expf(xv - m) * inv;
        bf16 h, l; split_bf16(v, h, l);
        Shb[(size_t)t * T + s] = h;
        Slb[(size_t)t * T + s] = l;
    }
}

// ---------------------------------------------------------------------------
// MLP2 split-K reduce: out = sum of 4 partials + bias
// ---------------------------------------------------------------------------
__global__ void mlp2_reduce(const float* __restrict__ part, const float* __restrict__ b2,
                            float* __restrict__ out)
{
    const size_t P = (size_t)BB * TT * EE;
    const size_t i = (size_t)blockIdx.x * blockDim.x + threadIdx.x;
    const int n = (int)(i & (EE - 1));
    out[i] = part[i] + part[i + P] + part[i + 2 * P] + part[i + 3 * P] + b2[n];
}

// ---------------------------------------------------------------------------
// Launch
// ---------------------------------------------------------------------------
extern "C" void kernel_launch(void* const* d_in, const int* in_sizes, int n_in,
                              void* d_out, int out_size)
{
    const float* X    = (const float*)d_in[0];
    const float* ln1g = (const float*)d_in[1];
    const float* ln1b = (const float*)d_in[2];
    const float* Wq   = (const float*)d_in[3];
    const float* bq   = (const float*)d_in[4];
    const float* Wk   = (const float*)d_in[5];
    const float* bk   = (const float*)d_in[6];
    const float* Wv   = (const float*)d_in[7];
    const float* bv   = (const float*)d_in[8];
    const float* ln2g = (const float*)d_in[9];
    const float* ln2b = (const float*)d_in[10];
    const float* W1   = (const float*)d_in[11];
    const float* b1   = (const float*)d_in[12];
    const float* W2   = (const float*)d_in[13];
    const float* b2   = (const float*)d_in[14];
    float* out = (float*)d_out;

    float *S, *cc, *part;
    bf16 *Sh, *Sl, *Xnh, *Xnl, *qh, *ql, *kh, *kl, *vh, *vl, *vth, *vtl;
    bf16 *cch, *ccl, *midh, *midl;
    bf16 *Wqh, *Wql, *Wkh, *Wkl, *Wvh, *Wvl, *W1h, *W1l, *W2h, *W2l;
    cudaGetSymbolAddress((void**)&S,    g_S);
    cudaGetSymbolAddress((void**)&Sh,   g_Sh);
    cudaGetSymbolAddress((void**)&Sl,   g_Sl);
    cudaGetSymbolAddress((void**)&Xnh,  g_Xnh);
    cudaGetSymbolAddress((void**)&Xnl,  g_Xnl);
    cudaGetSymbolAddress((void**)&qh,   g_qh);
    cudaGetSymbolAddress((void**)&ql,   g_ql);
    cudaGetSymbolAddress((void**)&kh,   g_kh);
    cudaGetSymbolAddress((void**)&kl,   g_kl);
    cudaGetSymbolAddress((void**)&vh,   g_vh);
    cudaGetSymbolAddress((void**)&vl,   g_vl);
    cudaGetSymbolAddress((void**)&vth,  g_vth);
    cudaGetSymbolAddress((void**)&vtl,  g_vtl);
    cudaGetSymbolAddress((void**)&cc,   g_cc);
    cudaGetSymbolAddress((void**)&cch,  g_cch);
    cudaGetSymbolAddress((void**)&ccl,  g_ccl);
    cudaGetSymbolAddress((void**)&midh, g_midh);
    cudaGetSymbolAddress((void**)&midl, g_midl);
    cudaGetSymbolAddress((void**)&Wqh,  g_Wqh);
    cudaGetSymbolAddress((void**)&Wql,  g_Wql);
    cudaGetSymbolAddress((void**)&Wkh,  g_Wkh);
    cudaGetSymbolAddress((void**)&Wkl,  g_Wkl);
    cudaGetSymbolAddress((void**)&Wvh,  g_Wvh);
    cudaGetSymbolAddress((void**)&Wvl,  g_Wvl);
    cudaGetSymbolAddress((void**)&W1h,  g_W1h);
    cudaGetSymbolAddress((void**)&W1l,  g_W1l);
    cudaGetSymbolAddress((void**)&W2h,  g_W2h);
    cudaGetSymbolAddress((void**)&W2l,  g_W2l);
    cudaGetSymbolAddress((void**)&part, g_part);

    const ZOff z0   = {1, 1, 0, 0};
    const ZOff oXn  = {HH, 1, (long)TT * EE, 0};
    const ZOff oWh  = {1, HH, 0, (long)EE * EE};
    const ZOff obh  = {1, HH, 0, (long)EE};
    const ZOff oQKV = {1, 1, (long)TT * EE, 0};
    const ZOff oS   = {1, 1, (long)TT * TT, 0};
    const ZOff oCC  = {HH, HH, (long)TT * DD, (long)EE};
    const ZOff oK1  = {1, 4, 0, 1024};                 // split-K A/B offset
    const ZOff oP   = {1, 4, 0, (long)BB * TT * EE};   // partial plane

    dim3 tb(32, 8);

    // 0. one-time weight split+transpose
    split_tr<<<dim3(4, 4, HH), tb>>>(Wq, Wqh, Wql, EE, EE);
    split_tr<<<dim3(4, 4, HH), tb>>>(Wk, Wkh, Wkl, EE, EE);
    split_tr<<<dim3(4, 4, HH), tb>>>(Wv, Wvh, Wvl, EE, EE);
    split_tr<<<dim3(FF / 32, DD / 32, 1), tb>>>(W1, W1h, W1l, DD, FF);
    split_tr<<<dim3(EE / 32, FF / 32, 1), tb>>>(W2, W2h, W2l, FF, EE);

    // 1. LN1 -> Xn planes
    ln_split<<<BB * TT, 128>>>(X, ln1g, ln1b, Xnh, Xnl, EE);

    // 2. Q,K,V projections -> planes
    dim3 gqkv(1, TT / 128, BB * HH);
    gemm_bt<1, 0><<<gqkv, 256>>>(Xnh, Xnl, Wqh, Wql, nullptr, qh, ql, bq,
                                 TT, EE, EE, EE, EE, EE, 1.f, oXn, oWh, oQKV, obh);
    gemm_bt<1, 0><<<gqkv, 256>>>(Xnh, Xnl, Wkh, Wkl, nullptr, kh, kl, bk,
                                 TT, EE, EE, EE, EE, EE, 1.f, oXn, oWh, oQKV, obh);
    gemm_bt<1, 0><<<gqkv, 256>>>(Xnh, Xnl, Wvh, Wvl, nullptr, vh, vl, bv,
                                 TT, EE, EE, EE, EE, EE, 1.f, oXn, oWh, oQKV, obh);

    // 3. scores = Q @ K^T / sqrt(E) -> f32 S (lower-triangle blocks only)
    dim3 gsc(TT / 128, TT / 128, BB * HH);
    gemm_bt<0, 1><<<gsc, 256>>>(qh, ql, kh, kl, S, nullptr, nullptr, nullptr,
                                TT, TT, EE, EE, EE, TT,
                                0.08838834764831845f, oQKV, oQKV, oS, z0);

    // 4. column softmax -> attn planes
    dim3 gsm(TT / 256, BB * HH);
    col_softmax<<<gsm, 256>>>(S, Sh, Sl, TT);

    // 4b. transpose V planes: [T][E] -> [E][T]
    tr_planes<<<dim3(EE / 32, TT / 32, BB * HH), tb>>>(vh, vl, vth, vtl, TT, EE);

    // 5. cc = attn @ V  (K truncated at diag block) -> f32 concat [B,T,D]
    dim3 gav(1, TT / 128, BB * HH);
    gemm_bt<0, 2><<<gav, 256>>>(Sh, Sl, vth, vtl, cc, nullptr, nullptr, nullptr,
                                TT, EE, TT, TT, TT, DD, 1.f, oS, oQKV, oCC, z0);

    // 6. LN2 -> cc planes
    ln_split<<<BB * TT, 256>>>(cc, ln2g, ln2b, cch, ccl, DD);

    // 7. mid = gelu(cc @ W1 + b1) -> planes
    dim3 g1(FF / 128, (BB * TT) / 128, 1);
    gemm_bt<2, 0><<<g1, 256>>>(cch, ccl, W1h, W1l, nullptr, midh, midl, b1,
                               BB * TT, FF, DD, DD, DD, FF, 1.f, z0, z0, z0, z0);

    // 8. out = mid @ W2 + b2 : split-K x4 into partials, then reduce
    dim3 g2(1, (BB * TT) / 128, 4);
    gemm_bt<0, 0><<<g2, 256>>>(midh, midl, W2h, W2l, part, nullptr, nullptr, nullptr,
                               BB * TT, EE, 1024, FF, FF, EE, 1.f, oK1, oK1, oP, z0);
    mlp2_reduce<<<(BB * TT * EE) / 256, 256>>>(part, b2, out);
}

// round 7
// speedup vs baseline: 1.6761x; 1.0377x over previous
#include <cuda_runtime.h>
#include <cuda_bf16.h>
#include <math.h>
#include <stdint.h>

#define BB 4
#define TT 2048
#define EE 128
#define HH 8
#define DD 1024
#define FF 4096

typedef __nv_bfloat16 bf16;

// ---------------------------------------------------------------------------
// Scratch (static device globals; no allocation anywhere)
// ---------------------------------------------------------------------------
__device__ float g_S  [(size_t)BB*HH*TT*TT];          // 512 MB f32 scores
__device__ bf16  g_Sh [(size_t)BB*HH*TT*TT];
__device__ bf16  g_Sl [(size_t)BB*HH*TT*TT];
__device__ bf16  g_Xnh[(size_t)BB*TT*EE], g_Xnl[(size_t)BB*TT*EE];
__device__ bf16  g_qh [(size_t)BB*HH*TT*EE], g_ql [(size_t)BB*HH*TT*EE];
__device__ bf16  g_kh [(size_t)BB*HH*TT*EE], g_kl [(size_t)BB*HH*TT*EE];
__device__ bf16  g_vh [(size_t)BB*HH*TT*EE], g_vl [(size_t)BB*HH*TT*EE];
__device__ bf16  g_vth[(size_t)BB*HH*TT*EE], g_vtl[(size_t)BB*HH*TT*EE];
__device__ float g_cc [(size_t)BB*TT*DD];
__device__ bf16  g_cch[(size_t)BB*TT*DD], g_ccl[(size_t)BB*TT*DD];
__device__ bf16  g_midh[(size_t)BB*TT*FF], g_midl[(size_t)BB*TT*FF];
__device__ bf16  g_Wqh[(size_t)HH*EE*EE], g_Wql[(size_t)HH*EE*EE];
__device__ bf16  g_Wkh[(size_t)HH*EE*EE], g_Wkl[(size_t)HH*EE*EE];
__device__ bf16  g_Wvh[(size_t)HH*EE*EE], g_Wvl[(size_t)HH*EE*EE];
__device__ bf16  g_W1h[(size_t)DD*FF],   g_W1l[(size_t)DD*FF];   // [F][D]
__device__ bf16  g_W2h[(size_t)FF*EE],   g_W2l[(size_t)FF*EE];   // [E][F]
__device__ float g_part[(size_t)4*BB*TT*EE];

// ---------------------------------------------------------------------------
struct ZOff { int dv; int md; long sd; long sm; };
__device__ __forceinline__ long zoff(ZOff o, int z) {
    return (long)(z / o.dv) * o.sd + (long)(z % o.md) * o.sm;
}

__device__ __forceinline__ void split_bf16(float x, bf16& h, bf16& l) {
    h = __float2bfloat16(x);
    l = __float2bfloat16(x - __bfloat162float(h));
}
__device__ __forceinline__ uint32_t pack2(bf16 a, bf16 b) {
    uint32_t ua = __bfloat16_as_ushort(a), ub = __bfloat16_as_ushort(b);
    return ua | (ub << 16);
}

__device__ __forceinline__ void mma_bf16(float& c0, float& c1, float& c2, float& c3,
                                         uint32_t a0, uint32_t a1, uint32_t a2, uint32_t a3,
                                         uint32_t b0, uint32_t b1) {
    asm volatile(
        "mma.sync.aligned.m16n8k16.row.col.f32.bf16.bf16.f32 "
        "{%0,%1,%2,%3}, {%4,%5,%6,%7}, {%8,%9}, {%0,%1,%2,%3};"
        : "+f"(c0), "+f"(c1), "+f"(c2), "+f"(c3)
        : "r"(a0), "r"(a1), "r"(a2), "r"(a3), "r"(b0), "r"(b1));
}

__device__ __forceinline__ void cpa16(bf16* smem, const bf16* gmem) {
    uint32_t s = (uint32_t)__cvta_generic_to_shared(smem);
    asm volatile("cp.async.cg.shared.global [%0], [%1], 16;" :: "r"(s), "l"(gmem));
}

// SMEM stage layout (elements of bf16):
//   Ah: [0, 5120)  Al: [5120, 10240)  Bh: [10240, 15360)  Bl: [15360, 20480)
// row stride 40. Two stages -> 40960 bf16 = 80 KB dynamic SMEM.
#define STAGE_ELEMS 20480
#define ROWS_LD 40

// ---------------------------------------------------------------------------
// GEMM on pre-split bf16 hi/lo planes. C = act(scale * A @ B^T + bias)
// A: [M][K] planes (lda), B: [N][K] planes (ldb).
//   EPI   : 0 f32*scale -> Cf ; 1 split+bias -> Ch/Cl ; 2 split+bias+gelu
//   CMODE : 0 normal; 1 skip blocks above diagonal; 2 truncate K at m0+128
// Block tile 128x128, BK=32, 256 threads, 2-stage cp.async pipeline.
// ---------------------------------------------------------------------------
template <int EPI, int CMODE>
__global__ __launch_bounds__(256, 2) void gemm_bt(
    const bf16* __restrict__ Ahg, const bf16* __restrict__ Alg,
    const bf16* __restrict__ Bhg, const bf16* __restrict__ Blg,
    float* __restrict__ Cf, bf16* __restrict__ Chg, bf16* __restrict__ Clg,
    const float* __restrict__ bias,
    int M, int N, int K, int lda, int ldb, int ldc, float scale,
    ZOff oa, ZOff ob, ZOff oc, ZOff obias)
{
    const int z = blockIdx.z;
    const long za = zoff(oa, z), zb = zoff(ob, z), zc = zoff(oc, z);
    Ahg += za; Alg += za;
    Bhg += zb; Blg += zb;
    if (EPI == 0) Cf += zc; else { Chg += zc; Clg += zc; }
    if (EPI >= 1) bias += zoff(obias, z);

    const int n0 = blockIdx.x * 128;
    const int m0 = blockIdx.y * 128;
    if (CMODE == 1 && m0 < n0) return;
    int kEnd = K;
    if (CMODE == 2) kEnd = min(K, m0 + 128);
    const int nIter = kEnd >> 5;

    extern __shared__ bf16 dyn[];

    const int tid  = threadIdx.x;
    const int lane = tid & 31;
    const int wid  = tid >> 5;
    const int wm   = wid & 3;
    const int wn   = wid >> 2;

    float acc[2][8][4];
#pragma unroll
    for (int i = 0; i < 2; i++)
#pragma unroll
        for (int j = 0; j < 8; j++)
#pragma unroll
            for (int r = 0; r < 4; r++) acc[i][j][r] = 0.f;

    // loaders: thread covers row lr, k-cols [lc, lc+16)
    const int lr = tid >> 1;
    const int lc = (tid & 1) * 16;
    const bf16* Agh = Ahg + (size_t)(m0 + lr) * lda + lc;
    const bf16* Agl = Alg + (size_t)(m0 + lr) * lda + lc;
    const bf16* Bgh = Bhg + (size_t)(n0 + lr) * ldb + lc;
    const bf16* Bgl = Blg + (size_t)(n0 + lr) * ldb + lc;
    const int ldst = lr * ROWS_LD + lc;

#define ISSUE(it, buf)                                                        \
    do {                                                                      \
        bf16* st = dyn + (buf) * STAGE_ELEMS;                                 \
        const int ko = (it) << 5;                                             \
        cpa16(st + ldst,         Agh + ko); cpa16(st + ldst + 8,     Agh + ko + 8); \
        cpa16(st + 5120 + ldst,  Agl + ko); cpa16(st + 5120 + ldst + 8,  Agl + ko + 8); \
        cpa16(st + 10240 + ldst, Bgh + ko); cpa16(st + 10240 + ldst + 8, Bgh + ko + 8); \
        cpa16(st + 15360 + ldst, Bgl + ko); cpa16(st + 15360 + ldst + 8, Bgl + ko + 8); \
        asm volatile("cp.async.commit_group;");                               \
    } while (0)

    ISSUE(0, 0);

    for (int it = 0; it < nIter; it++) {
        if (it + 1 < nIter) {
            ISSUE(it + 1, (it + 1) & 1);
            asm volatile("cp.async.wait_group 1;" ::: "memory");
        } else {
            asm volatile("cp.async.wait_group 0;" ::: "memory");
        }
        __syncthreads();

        const bf16* st = dyn + (it & 1) * STAGE_ELEMS;
        const bf16* sAh = st;
        const bf16* sAl = st + 5120;
        const bf16* sBh = st + 10240;
        const bf16* sBl = st + 15360;

#pragma unroll
        for (int s = 0; s < 2; s++) {
            const int kk = s * 16;
            uint32_t ah[2][4], al[2][4];
#pragma unroll
            for (int mt = 0; mt < 2; mt++) {
                const int am = wm * 32 + mt * 16 + (lane >> 2);
                const int acol = kk + (lane & 3) * 2;
                ah[mt][0] = *(const uint32_t*)&sAh[am * ROWS_LD + acol];
                ah[mt][1] = *(const uint32_t*)&sAh[(am + 8) * ROWS_LD + acol];
                ah[mt][2] = *(const uint32_t*)&sAh[am * ROWS_LD + acol + 8];
                ah[mt][3] = *(const uint32_t*)&sAh[(am + 8) * ROWS_LD + acol + 8];
                al[mt][0] = *(const uint32_t*)&sAl[am * ROWS_LD + acol];
                al[mt][1] = *(const uint32_t*)&sAl[(am + 8) * ROWS_LD + acol];
                al[mt][2] = *(const uint32_t*)&sAl[am * ROWS_LD + acol + 8];
                al[mt][3] = *(const uint32_t*)&sAl[(am + 8) * ROWS_LD + acol + 8];
            }
#pragma unroll
            for (int nt = 0; nt < 8; nt++) {
                const int bcol = wn * 64 + nt * 8 + (lane >> 2);
                const int kb2  = kk + (lane & 3) * 2;
                uint32_t bh0 = *(const uint32_t*)&sBh[bcol * ROWS_LD + kb2];
                uint32_t bh1 = *(const uint32_t*)&sBh[bcol * ROWS_LD + kb2 + 8];
                uint32_t bl0 = *(const uint32_t*)&sBl[bcol * ROWS_LD + kb2];
                uint32_t bl1 = *(const uint32_t*)&sBl[bcol * ROWS_LD + kb2 + 8];
#pragma unroll
                for (int mt = 0; mt < 2; mt++) {
                    float* c = acc[mt][nt];
                    mma_bf16(c[0], c[1], c[2], c[3],
                             ah[mt][0], ah[mt][1], ah[mt][2], ah[mt][3], bh0, bh1);
                    mma_bf16(c[0], c[1], c[2], c[3],
                             ah[mt][0], ah[mt][1], ah[mt][2], ah[mt][3], bl0, bl1);
                    mma_bf16(c[0], c[1], c[2], c[3],
                             al[mt][0], al[mt][1], al[mt][2], al[mt][3], bh0, bh1);
                }
            }
        }
        __syncthreads();
    }
#undef ISSUE

    // epilogue
#pragma unroll
    for (int mt = 0; mt < 2; mt++) {
#pragma unroll
        for (int nt = 0; nt < 8; nt++) {
            const int r0 = m0 + wm * 32 + mt * 16 + (lane >> 2);
            const int cb = n0 + wn * 64 + nt * 8 + (lane & 3) * 2;
            float v[4];
#pragma unroll
            for (int r = 0; r < 4; r++) v[r] = acc[mt][nt][r] * scale;
            if (EPI >= 1) {
                float b0 = bias[cb], b1 = bias[cb + 1];
                v[0] += b0; v[1] += b1; v[2] += b0; v[3] += b1;
            }
            if (EPI == 2) {
#pragma unroll
                for (int r = 0; r < 4; r++)
                    v[r] = 0.5f * v[r] * (1.0f + erff(v[r] * 0.70710678118654752f));
            }
            if (EPI == 0) {
                *(float2*)&Cf[(size_t)r0 * ldc + cb]       = make_float2(v[0], v[1]);
                *(float2*)&Cf[(size_t)(r0 + 8) * ldc + cb] = make_float2(v[2], v[3]);
            } else {
                bf16 h0, l0, h1, l1;
                split_bf16(v[0], h0, l0); split_bf16(v[1], h1, l1);
                *(uint32_t*)&Chg[(size_t)r0 * ldc + cb] = pack2(h0, h1);
                *(uint32_t*)&Clg[(size_t)r0 * ldc + cb] = pack2(l0, l1);
                split_bf16(v[2], h0, l0); split_bf16(v[3], h1, l1);
                *(uint32_t*)&Chg[(size_t)(r0 + 8) * ldc + cb] = pack2(h0, h1);
                *(uint32_t*)&Clg[(size_t)(r0 + 8) * ldc + cb] = pack2(l0, l1);
            }
        }
    }
}

// ---------------------------------------------------------------------------
__global__ void split_tr(const float* __restrict__ src, bf16* __restrict__ oh,
                         bf16* __restrict__ ol, int R, int C)
{
    __shared__ float t[32][33];
    const size_t zo = (size_t)blockIdx.z * R * C;
    const int c0 = blockIdx.x * 32, r0 = blockIdx.y * 32;
    const int tx = threadIdx.x, ty = threadIdx.y;
    for (int i = ty; i < 32; i += 8)
        t[i][tx] = src[zo + (size_t)(r0 + i) * C + c0 + tx];
    __syncthreads();
    for (int i = ty; i < 32; i += 8) {
        float v = t[tx][i];
        bf16 h, l; split_bf16(v, h, l);
        oh[zo + (size_t)(c0 + i) * R + r0 + tx] = h;
        ol[zo + (size_t)(c0 + i) * R + r0 + tx] = l;
    }
}

__global__ void tr_planes(const bf16* __restrict__ ih, const bf16* __restrict__ il,
                          bf16* __restrict__ oh, bf16* __restrict__ ol, int R, int C)
{
    __shared__ bf16 th[32][33], tl[32][33];
    const size_t zo = (size_t)blockIdx.z * R * C;
    const int c0 = blockIdx.x * 32, r0 = blockIdx.y * 32;
    const int tx = threadIdx.x, ty = threadIdx.y;
    for (int i = ty; i < 32; i += 8) {
        th[i][tx] = ih[zo + (size_t)(r0 + i) * C + c0 + tx];
        tl[i][tx] = il[zo + (size_t)(r0 + i) * C + c0 + tx];
    }
    __syncthreads();
    for (int i = ty; i < 32; i += 8) {
        oh[zo + (size_t)(c0 + i) * R + r0 + tx] = th[tx][i];
        ol[zo + (size_t)(c0 + i) * R + r0 + tx] = tl[tx][i];
    }
}

// ---------------------------------------------------------------------------
__global__ void ln_split(const float* __restrict__ x, const float* __restrict__ g,
                         const float* __restrict__ b, bf16* __restrict__ yh,
                         bf16* __restrict__ yl, int D)
{
    const long row = blockIdx.x;
    const float* xr = x + row * D;

    float s = 0.f, s2 = 0.f;
    for (int i = threadIdx.x; i < D; i += blockDim.x) {
        float v = xr[i];
        s += v; s2 += v * v;
    }
#pragma unroll
    for (int o = 16; o; o >>= 1) {
        s  += __shfl_xor_sync(0xFFFFFFFFu, s,  o);
        s2 += __shfl_xor_sync(0xFFFFFFFFu, s2, o);
    }
    __shared__ float shs[8], shs2[8];
    __shared__ float mu_s, ri_s;
    const int w = threadIdx.x >> 5, l = threadIdx.x & 31;
    if (l == 0) { shs[w] = s; shs2[w] = s2; }
    __syncthreads();
    if (threadIdx.x == 0) {
        const int nw = blockDim.x >> 5;
        float ts = 0.f, ts2 = 0.f;
        for (int i = 0; i < nw; i++) { ts += shs[i]; ts2 += shs2[i]; }
        float mu  = ts / D;
        float var = ts2 / D - mu * mu;
        mu_s = mu;
        ri_s = rsqrtf(var + 1e-5f);
    }
    __syncthreads();
    const float mu = mu_s, ri = ri_s;
    for (int i = threadIdx.x; i < D; i += blockDim.x) {
        float v = (xr[i] - mu) * ri * g[i] + b[i];
        bf16 h, lo; split_bf16(v, h, lo);
        yh[row * D + i] = h;
        yl[row * D + i] = lo;
    }
}

// ---------------------------------------------------------------------------
__global__ void col_softmax(const float* __restrict__ S, bf16* __restrict__ Sh,
                            bf16* __restrict__ Sl, int T)
{
    const int s  = blockIdx.x * blockDim.x + threadIdx.x;
    const int t0 = blockIdx.x * blockDim.x;
    const size_t zo = (size_t)blockIdx.y * T * T;
    const float* Sb = S + zo;
    bf16* Shb = Sh + zo;
    bf16* Slb = Sl + zo;

    float m = -INFINITY, zden = 0.f;
    for (int t = t0; t < T; ++t) {
        if (t >= s) {
            float xv = Sb[(size_t)t * T + s];
            float mn = fmaxf(m, xv);
            zden = zden * __expf(m - mn) + __expf(xv - mn);
            m = mn;
        }
    }
    const float inv = 1.f / zden;

    const bf16 z16 = __float2bfloat16(0.f);
    for (int t = (s & ~127); t < s; ++t) {
        Shb[(size_t)t * T + s] = z16;
        Slb[(size_t)t * T + s] = z16;
    }
    for (int t = s; t < T; ++t) {
        float xv = Sb[(size_t)t * T + s];
        float v = __expf(xv - m) * inv;
        bf16 h, l; split_bf16(v, h, l);
        Shb[(size_t)t * T + s] = h;
        Slb[(size_t)t * T + s] = l;
    }
}

// ---------------------------------------------------------------------------
__global__ void mlp2_reduce(const float* __restrict__ part, const float* __restrict__ b2,
                            float* __restrict__ out)
{
    const size_t P = (size_t)BB * TT * EE;
    const size_t i = (size_t)blockIdx.x * blockDim.x + threadIdx.x;
    const int n = (int)(i & (EE - 1));
    out[i] = part[i] + part[i + P] + part[i + 2 * P] + part[i + 3 * P] + b2[n];
}

// ---------------------------------------------------------------------------
extern "C" void kernel_launch(void* const* d_in, const int* in_sizes, int n_in,
                              void* d_out, int out_size)
{
    const float* X    = (const float*)d_in[0];
    const float* ln1g = (const float*)d_in[1];
    const float* ln1b = (const float*)d_in[2];
    const float* Wq   = (const float*)d_in[3];
    const float* bq   = (const float*)d_in[4];
    const float* Wk   = (const float*)d_in[5];
    const float* bk   = (const float*)d_in[6];
    const float* Wv   = (const float*)d_in[7];
    const float* bv   = (const float*)d_in[8];
    const float* ln2g = (const float*)d_in[9];
    const float* ln2b = (const float*)d_in[10];
    const float* W1   = (const float*)d_in[11];
    const float* b1   = (const float*)d_in[12];
    const float* W2   = (const float*)d_in[13];
    const float* b2   = (const float*)d_in[14];
    float* out = (float*)d_out;

    float *S, *cc, *part;
    bf16 *Sh, *Sl, *Xnh, *Xnl, *qh, *ql, *kh, *kl, *vh, *vl, *vth, *vtl;
    bf16 *cch, *ccl, *midh, *midl;
    bf16 *Wqh, *Wql, *Wkh, *Wkl, *Wvh, *Wvl, *W1h, *W1l, *W2h, *W2l;
    cudaGetSymbolAddress((void**)&S,    g_S);
    cudaGetSymbolAddress((void**)&Sh,   g_Sh);
    cudaGetSymbolAddress((void**)&Sl,   g_Sl);
    cudaGetSymbolAddress((void**)&Xnh,  g_Xnh);
    cudaGetSymbolAddress((void**)&Xnl,  g_Xnl);
    cudaGetSymbolAddress((void**)&qh,   g_qh);
    cudaGetSymbolAddress((void**)&ql,   g_ql);
    cudaGetSymbolAddress((void**)&kh,   g_kh);
    cudaGetSymbolAddress((void**)&kl,   g_kl);
    cudaGetSymbolAddress((void**)&vh,   g_vh);
    cudaGetSymbolAddress((void**)&vl,   g_vl);
    cudaGetSymbolAddress((void**)&vth,  g_vth);
    cudaGetSymbolAddress((void**)&vtl,  g_vtl);
    cudaGetSymbolAddress((void**)&cc,   g_cc);
    cudaGetSymbolAddress((void**)&cch,  g_cch);
    cudaGetSymbolAddress((void**)&ccl,  g_ccl);
    cudaGetSymbolAddress((void**)&midh, g_midh);
    cudaGetSymbolAddress((void**)&midl, g_midl);
    cudaGetSymbolAddress((void**)&Wqh,  g_Wqh);
    cudaGetSymbolAddress((void**)&Wql,  g_Wql);
    cudaGetSymbolAddress((void**)&Wkh,  g_Wkh);
    cudaGetSymbolAddress((void**)&Wkl,  g_Wkl);
    cudaGetSymbolAddress((void**)&Wvh,  g_Wvh);
    cudaGetSymbolAddress((void**)&Wvl,  g_Wvl);
    cudaGetSymbolAddress((void**)&W1h,  g_W1h);
    cudaGetSymbolAddress((void**)&W1l,  g_W1l);
    cudaGetSymbolAddress((void**)&W2h,  g_W2h);
    cudaGetSymbolAddress((void**)&W2l,  g_W2l);
    cudaGetSymbolAddress((void**)&part, g_part);

    const ZOff z0   = {1, 1, 0, 0};
    const ZOff oXn  = {HH, 1, (long)TT * EE, 0};
    const ZOff oWh  = {1, HH, 0, (long)EE * EE};
    const ZOff obh  = {1, HH, 0, (long)EE};
    const ZOff oQKV = {1, 1, (long)TT * EE, 0};
    const ZOff oS   = {1, 1, (long)TT * TT, 0};
    const ZOff oCC  = {HH, HH, (long)TT * DD, (long)EE};
    const ZOff oK1  = {1, 4, 0, 1024};
    const ZOff oP   = {1, 4, 0, (long)BB * TT * EE};

    const int SMEM = 2 * STAGE_ELEMS * (int)sizeof(bf16);   // 80 KB
    cudaFuncSetAttribute(gemm_bt<0, 0>, cudaFuncAttributeMaxDynamicSharedMemorySize, SMEM);
    cudaFuncSetAttribute(gemm_bt<0, 1>, cudaFuncAttributeMaxDynamicSharedMemorySize, SMEM);
    cudaFuncSetAttribute(gemm_bt<0, 2>, cudaFuncAttributeMaxDynamicSharedMemorySize, SMEM);
    cudaFuncSetAttribute(gemm_bt<1, 0>, cudaFuncAttributeMaxDynamicSharedMemorySize, SMEM);
    cudaFuncSetAttribute(gemm_bt<2, 0>, cudaFuncAttributeMaxDynamicSharedMemorySize, SMEM);

    dim3 tb(32, 8);

    // 0. one-time weight split+transpose
    split_tr<<<dim3(4, 4, HH), tb>>>(Wq, Wqh, Wql, EE, EE);
    split_tr<<<dim3(4, 4, HH), tb>>>(Wk, Wkh, Wkl, EE, EE);
    split_tr<<<dim3(4, 4, HH), tb>>>(Wv, Wvh, Wvl, EE, EE);
    split_tr<<<dim3(FF / 32, DD / 32, 1), tb>>>(W1, W1h, W1l, DD, FF);
    split_tr<<<dim3(EE / 32, FF / 32, 1), tb>>>(W2, W2h, W2l, FF, EE);

    // 1. LN1 -> Xn planes
    ln_split<<<BB * TT, 128>>>(X, ln1g, ln1b, Xnh, Xnl, EE);

    // 2. Q,K,V projections -> planes
    dim3 gqkv(1, TT / 128, BB * HH);
    gemm_bt<1, 0><<<gqkv, 256, SMEM>>>(Xnh, Xnl, Wqh, Wql, nullptr, qh, ql, bq,
                                       TT, EE, EE, EE, EE, EE, 1.f, oXn, oWh, oQKV, obh);
    gemm_bt<1, 0><<<gqkv, 256, SMEM>>>(Xnh, Xnl, Wkh, Wkl, nullptr, kh, kl, bk,
                                       TT, EE, EE, EE, EE, EE, 1.f, oXn, oWh, oQKV, obh);
    gemm_bt<1, 0><<<gqkv, 256, SMEM>>>(Xnh, Xnl, Wvh, Wvl, nullptr, vh, vl, bv,
                                       TT, EE, EE, EE, EE, EE, 1.f, oXn, oWh, oQKV, obh);

    // 3. scores = Q @ K^T / sqrt(E) -> f32 S (lower-triangle blocks only)
    dim3 gsc(TT / 128, TT / 128, BB * HH);
    gemm_bt<0, 1><<<gsc, 256, SMEM>>>(qh, ql, kh, kl, S, nullptr, nullptr, nullptr,
                                      TT, TT, EE, EE, EE, TT,
                                      0.08838834764831845f, oQKV, oQKV, oS, z0);

    // 4. column softmax -> attn planes
    dim3 gsm(TT / 256, BB * HH);
    col_softmax<<<gsm, 256>>>(S, Sh, Sl, TT);

    // 4b. transpose V planes: [T][E] -> [E][T]
    tr_planes<<<dim3(EE / 32, TT / 32, BB * HH), tb>>>(vh, vl, vth, vtl, TT, EE);

    // 5. cc = attn @ V (K truncated at diag block) -> f32 concat [B,T,D]
    dim3 gav(1, TT / 128, BB * HH);
    gemm_bt<0, 2><<<gav, 256, SMEM>>>(Sh, Sl, vth, vtl, cc, nullptr, nullptr, nullptr,
                                      TT, EE, TT, TT, TT, DD, 1.f, oS, oQKV, oCC, z0);

    // 6. LN2 -> cc planes
    ln_split<<<BB * TT, 256>>>(cc, ln2g, ln2b, cch, ccl, DD);

    // 7. mid = gelu(cc @ W1 + b1) -> planes
    dim3 g1(FF / 128, (BB * TT) / 128, 1);
    gemm_bt<2, 0><<<g1, 256, SMEM>>>(cch, ccl, W1h, W1l, nullptr, midh, midl, b1,
                                     BB * TT, FF, DD, DD, DD, FF, 1.f, z0, z0, z0, z0);

    // 8. out = mid @ W2 + b2 : split-K x4, then reduce
    dim3 g2(1, (BB * TT) / 128, 4);
    gemm_bt<0, 0><<<g2, 256, SMEM>>>(midh, midl, W2h, W2l, part, nullptr, nullptr, nullptr,
                                     BB * TT, EE, 1024, FF, FF, EE, 1.f, oK1, oK1, oP, z0);
    mlp2_reduce<<<(BB * TT * EE) / 256, 256>>>(part, b2, out);
}

// round 10
// speedup vs baseline: 3.6753x; 2.1927x over previous
#include <cuda_runtime.h>
#include <cuda_bf16.h>
#include <math.h>
#include <stdint.h>

// R10 = R9 resubmission (R9 failed on infra: container never ran the binary).
// Core changes vs. last PASSING kernel (R7, 3098.7us):
//   * ldmatrix (non-trans, matching [row][k] operand storage) for all MMA
//     fragment loads -> ~4x fewer shared-load instructions in the hot loop
//   * scores GEMM epilogue fused: exp + causal zero + column partial sums,
//     attn written straight to bf16 hi/lo planes (f32 S buffer deleted)
//   * colsum -> inv folded into the V transpose (out = e @ (inv*V))

#define BB 4
#define TT 2048
#define EE 128
#define HH 8
#define DD 1024
#define FF 4096

typedef __nv_bfloat16 bf16;

// ---------------------------------------------------------------------------
// Scratch (static device globals; no allocation anywhere)
// ---------------------------------------------------------------------------
__device__ bf16  g_Sh [(size_t)BB*HH*TT*TT];          // attn e hi plane
__device__ bf16  g_Sl [(size_t)BB*HH*TT*TT];          // attn e lo plane
__device__ float g_psum[(size_t)BB*HH*(TT/128)*TT];   // per-mblock column sums
__device__ float g_inv [(size_t)BB*HH*TT];            // 1/colsum
__device__ bf16  g_Xnh[(size_t)BB*TT*EE], g_Xnl[(size_t)BB*TT*EE];
__device__ bf16  g_qh [(size_t)BB*HH*TT*EE], g_ql [(size_t)BB*HH*TT*EE];
__device__ bf16  g_kh [(size_t)BB*HH*TT*EE], g_kl [(size_t)BB*HH*TT*EE];
__device__ bf16  g_vh [(size_t)BB*HH*TT*EE], g_vl [(size_t)BB*HH*TT*EE];
__device__ bf16  g_vth[(size_t)BB*HH*TT*EE], g_vtl[(size_t)BB*HH*TT*EE];
__device__ float g_cc [(size_t)BB*TT*DD];
__device__ bf16  g_cch[(size_t)BB*TT*DD], g_ccl[(size_t)BB*TT*DD];
__device__ bf16  g_midh[(size_t)BB*TT*FF], g_midl[(size_t)BB*TT*FF];
__device__ bf16  g_Wqh[(size_t)HH*EE*EE], g_Wql[(size_t)HH*EE*EE];
__device__ bf16  g_Wkh[(size_t)HH*EE*EE], g_Wkl[(size_t)HH*EE*EE];
__device__ bf16  g_Wvh[(size_t)HH*EE*EE], g_Wvl[(size_t)HH*EE*EE];
__device__ bf16  g_W1h[(size_t)DD*FF],   g_W1l[(size_t)DD*FF];   // [F][D]
__device__ bf16  g_W2h[(size_t)FF*EE],   g_W2l[(size_t)FF*EE];   // [E][F]
__device__ float g_part[(size_t)4*BB*TT*EE];

// ---------------------------------------------------------------------------
struct ZOff { int dv; int md; long sd; long sm; };
__device__ __forceinline__ long zoff(ZOff o, int z) {
    return (long)(z / o.dv) * o.sd + (long)(z % o.md) * o.sm;
}

__device__ __forceinline__ void split_bf16(float x, bf16& h, bf16& l) {
    h = __float2bfloat16(x);
    l = __float2bfloat16(x - __bfloat162float(h));
}
__device__ __forceinline__ uint32_t pack2(bf16 a, bf16 b) {
    uint32_t ua = __bfloat16_as_ushort(a), ub = __bfloat16_as_ushort(b);
    return ua | (ub << 16);
}

__device__ __forceinline__ void mma_bf16(float* c,
                                         const uint32_t* a, uint32_t b0, uint32_t b1) {
    asm volatile(
        "mma.sync.aligned.m16n8k16.row.col.f32.bf16.bf16.f32 "
        "{%0,%1,%2,%3}, {%4,%5,%6,%7}, {%8,%9}, {%0,%1,%2,%3};"
        : "+f"(c[0]), "+f"(c[1]), "+f"(c[2]), "+f"(c[3])
        : "r"(a[0]), "r"(a[1]), "r"(a[2]), "r"(a[3]), "r"(b0), "r"(b1));
}

__device__ __forceinline__ void ldsm4(uint32_t* r, const bf16* p) {
    uint32_t a = (uint32_t)__cvta_generic_to_shared(p);
    asm volatile("ldmatrix.sync.aligned.m8n8.x4.shared.b16 {%0,%1,%2,%3}, [%4];"
        : "=r"(r[0]), "=r"(r[1]), "=r"(r[2]), "=r"(r[3]) : "r"(a));
}

__device__ __forceinline__ void cpa16(bf16* smem, const bf16* gmem) {
    uint32_t s = (uint32_t)__cvta_generic_to_shared(smem);
    asm volatile("cp.async.cg.shared.global [%0], [%1], 16;" :: "r"(s), "l"(gmem));
}

// SMEM stage layout (bf16 elems): Ah[0,5120) Al[5120,..) Bh[10240,..) Bl[15360,..)
// row stride 40. Two stages = 80 KB dynamic SMEM.
#define STAGE_ELEMS 20480
#define ROWS_LD 40

// ---------------------------------------------------------------------------
// GEMM on pre-split bf16 hi/lo planes. C = act(scale * A @ B^T + bias)
//   EPI   : 0 f32*scale -> Cf ; 1 split+bias -> planes ; 2 +gelu -> planes
//           3 exp(scale*acc), causal zero (m<n), -> planes + column psums
//   CMODE : 0 normal; 1 skip blocks above diagonal; 2 truncate K at m0+128
// ---------------------------------------------------------------------------
template <int EPI, int CMODE>
__global__ __launch_bounds__(256, 2) void gemm_bt(
    const bf16* __restrict__ Ahg, const bf16* __restrict__ Alg,
    const bf16* __restrict__ Bhg, const bf16* __restrict__ Blg,
    float* __restrict__ Cf, bf16* __restrict__ Chg, bf16* __restrict__ Clg,
    const float* __restrict__ bias, float* __restrict__ psum,
    int M, int N, int K, int lda, int ldb, int ldc, float scale,
    ZOff oa, ZOff ob, ZOff oc, ZOff obias)
{
    const int z = blockIdx.z;
    const long za = zoff(oa, z), zb = zoff(ob, z), zc = zoff(oc, z);
    Ahg += za; Alg += za;
    Bhg += zb; Blg += zb;
    if (EPI == 0) Cf += zc; else { Chg += zc; Clg += zc; }
    if (EPI == 1 || EPI == 2) bias += zoff(obias, z);

    const int n0 = blockIdx.x * 128;
    const int m0 = blockIdx.y * 128;
    if (CMODE == 1 && m0 < n0) return;
    int kEnd = K;
    if (CMODE == 2) kEnd = min(K, m0 + 128);
    const int nIter = kEnd >> 5;

    extern __shared__ bf16 dyn[];
    __shared__ float scol[8][128];

    const int tid  = threadIdx.x;
    const int lane = tid & 31;
    const int wid  = tid >> 5;
    const int wm   = wid & 3;
    const int wn   = wid >> 2;

    float acc[2][8][4];
#pragma unroll
    for (int i = 0; i < 2; i++)
#pragma unroll
        for (int j = 0; j < 8; j++)
#pragma unroll
            for (int r = 0; r < 4; r++) acc[i][j][r] = 0.f;

    // cp.async loaders
    const int lr = tid >> 1;
    const int lc = (tid & 1) * 16;
    const bf16* Agh = Ahg + (size_t)(m0 + lr) * lda + lc;
    const bf16* Agl = Alg + (size_t)(m0 + lr) * lda + lc;
    const bf16* Bgh = Bhg + (size_t)(n0 + lr) * ldb + lc;
    const bf16* Bgl = Blg + (size_t)(n0 + lr) * ldb + lc;
    const int ldst = lr * ROWS_LD + lc;

    // ldmatrix per-lane offsets (non-trans; operands stored [row][k])
    const int m8 = lane >> 3, r8 = lane & 7;
    const int aoff = (wm * 32 + (m8 & 1) * 8 + r8) * ROWS_LD + (m8 >> 1) * 8;
    const int boff = (wn * 64 + (m8 >> 1) * 8 + r8) * ROWS_LD + (m8 & 1) * 8;

#define ISSUE(it, buf)                                                        \
    do {                                                                      \
        bf16* st = dyn + (buf) * STAGE_ELEMS;                                 \
        const int ko = (it) << 5;                                             \
        cpa16(st + ldst,         Agh + ko); cpa16(st + ldst + 8,         Agh + ko + 8); \
        cpa16(st + 5120 + ldst,  Agl + ko); cpa16(st + 5120 + ldst + 8,  Agl + ko + 8); \
        cpa16(st + 10240 + ldst, Bgh + ko); cpa16(st + 10240 + ldst + 8, Bgh + ko + 8); \
        cpa16(st + 15360 + ldst, Bgl + ko); cpa16(st + 15360 + ldst + 8, Bgl + ko + 8); \
        asm volatile("cp.async.commit_group;");                               \
    } while (0)

    ISSUE(0, 0);

    for (int it = 0; it < nIter; it++) {
        if (it + 1 < nIter) {
            ISSUE(it + 1, (it + 1) & 1);
            asm volatile("cp.async.wait_group 1;" ::: "memory");
        } else {
            asm volatile("cp.async.wait_group 0;" ::: "memory");
        }
        __syncthreads();

        const bf16* st = dyn + (it & 1) * STAGE_ELEMS;
        const bf16* sAh = st;
        const bf16* sAl = st + 5120;
        const bf16* sBh = st + 10240;
        const bf16* sBl = st + 15360;

#pragma unroll
        for (int s = 0; s < 2; s++) {
            const int kk = s * 16;
            uint32_t ah[2][4], al[2][4];
            ldsm4(ah[0], sAh + aoff + kk);
            ldsm4(ah[1], sAh + aoff + 640 + kk);
            ldsm4(al[0], sAl + aoff + kk);
            ldsm4(al[1], sAl + aoff + 640 + kk);
#pragma unroll
            for (int ntp = 0; ntp < 4; ntp++) {
                uint32_t bh[4], bl[4];
                ldsm4(bh, sBh + boff + ntp * 640 + kk);
                ldsm4(bl, sBl + boff + ntp * 640 + kk);
#pragma unroll
                for (int j = 0; j < 2; j++) {
#pragma unroll
                    for (int mt = 0; mt < 2; mt++) {
                        float* c = acc[mt][2 * ntp + j];
                        mma_bf16(c, ah[mt], bh[2 * j], bh[2 * j + 1]);
                        mma_bf16(c, ah[mt], bl[2 * j], bl[2 * j + 1]);
                        mma_bf16(c, al[mt], bh[2 * j], bh[2 * j + 1]);
                    }
                }
            }
        }
        __syncthreads();
    }
#undef ISSUE

    // ---------------- epilogue ----------------
#pragma unroll
    for (int mt = 0; mt < 2; mt++) {
#pragma unroll
        for (int nt = 0; nt < 8; nt++) {
            const int r0 = m0 + wm * 32 + mt * 16 + (lane >> 2);
            const int cb = n0 + wn * 64 + nt * 8 + (lane & 3) * 2;
            float v[4];
#pragma unroll
            for (int r = 0; r < 4; r++) v[r] = acc[mt][nt][r] * scale;
            if (EPI == 1 || EPI == 2) {
                float b0 = bias[cb], b1 = bias[cb + 1];
                v[0] += b0; v[1] += b1; v[2] += b0; v[3] += b1;
            }
            if (EPI == 2) {
#pragma unroll
                for (int r = 0; r < 4; r++)
                    v[r] = 0.5f * v[r] * (1.0f + erff(v[r] * 0.70710678118654752f));
            }
            if (EPI == 3) {
                v[0] = (r0 < cb)         ? 0.f : __expf(v[0]);
                v[1] = (r0 < cb + 1)     ? 0.f : __expf(v[1]);
                v[2] = (r0 + 8 < cb)     ? 0.f : __expf(v[2]);
                v[3] = (r0 + 8 < cb + 1) ? 0.f : __expf(v[3]);
                float s0 = v[0] + v[2], s1 = v[1] + v[3];
#pragma unroll
                for (int o = 4; o < 32; o <<= 1) {
                    s0 += __shfl_xor_sync(0xFFFFFFFFu, s0, o);
                    s1 += __shfl_xor_sync(0xFFFFFFFFu, s1, o);
                }
                if (lane < 4) {
                    scol[wm * 2 + mt][wn * 64 + nt * 8 + lane * 2]     = s0;
                    scol[wm * 2 + mt][wn * 64 + nt * 8 + lane * 2 + 1] = s1;
                }
            }
            if (EPI == 0) {
                *(float2*)&Cf[(size_t)r0 * ldc + cb]       = make_float2(v[0], v[1]);
                *(float2*)&Cf[(size_t)(r0 + 8) * ldc + cb] = make_float2(v[2], v[3]);
            } else {
                bf16 h0, l0, h1, l1;
                split_bf16(v[0], h0, l0); split_bf16(v[1], h1, l1);
                *(uint32_t*)&Chg[(size_t)r0 * ldc + cb] = pack2(h0, h1);
                *(uint32_t*)&Clg[(size_t)r0 * ldc + cb] = pack2(l0, l1);
                split_bf16(v[2], h0, l0); split_bf16(v[3], h1, l1);
                *(uint32_t*)&Chg[(size_t)(r0 + 8) * ldc + cb] = pack2(h0, h1);
                *(uint32_t*)&Clg[(size_t)(r0 + 8) * ldc + cb] = pack2(l0, l1);
            }
        }
    }

    if (EPI == 3) {
        __syncthreads();
        if (tid < 128) {
            float p = 0.f;
#pragma unroll
            for (int sl = 0; sl < 8; sl++) p += scol[sl][tid];
            psum[((size_t)z * (TT / 128) + blockIdx.y) * TT + n0 + tid] = p;
        }
    }
}

// ---------------------------------------------------------------------------
// inv[s] = 1 / sum over valid m-blocks of psum
// ---------------------------------------------------------------------------
__global__ void colsum_inv(const float* __restrict__ psum, float* __restrict__ inv)
{
    const int s = blockIdx.x * blockDim.x + threadIdx.x;
    const int z = blockIdx.y;
    float sum = 0.f;
    for (int mb = s >> 7; mb < TT / 128; mb++)
        sum += psum[((size_t)z * (TT / 128) + mb) * TT + s];
    inv[(size_t)z * TT + s] = 1.f / sum;
}

// ---------------------------------------------------------------------------
__global__ void split_tr(const float* __restrict__ src, bf16* __restrict__ oh,
                         bf16* __restrict__ ol, int R, int C)
{
    __shared__ float t[32][33];
    const size_t zo = (size_t)blockIdx.z * R * C;
    const int c0 = blockIdx.x * 32, r0 = blockIdx.y * 32;
    const int tx = threadIdx.x, ty = threadIdx.y;
    for (int i = ty; i < 32; i += 8)
        t[i][tx] = src[zo + (size_t)(r0 + i) * C + c0 + tx];
    __syncthreads();
    for (int i = ty; i < 32; i += 8) {
        float v = t[tx][i];
        bf16 h, l; split_bf16(v, h, l);
        oh[zo + (size_t)(c0 + i) * R + r0 + tx] = h;
        ol[zo + (size_t)(c0 + i) * R + r0 + tx] = l;
    }
}

// Transpose V planes [T][E] -> [E][T], scaling row t by inv[t] (fp32 combine).
__global__ void tr_planes_scaled(const bf16* __restrict__ ih, const bf16* __restrict__ il,
                                 const float* __restrict__ inv,
                                 bf16* __restrict__ oh, bf16* __restrict__ ol,
                                 int R, int C)
{
    __shared__ bf16 th[32][33], tl[32][33];
    const size_t zo = (size_t)blockIdx.z * R * C;
    const int c0 = blockIdx.x * 32, r0 = blockIdx.y * 32;
    const int tx = threadIdx.x, ty = threadIdx.y;
    for (int i = ty; i < 32; i += 8) {
        th[i][tx] = ih[zo + (size_t)(r0 + i) * C + c0 + tx];
        tl[i][tx] = il[zo + (size_t)(r0 + i) * C + c0 + tx];
    }
    __syncthreads();
    const float invv = inv[(size_t)blockIdx.z * R + r0 + tx];
    for (int i = ty; i < 32; i += 8) {
        float v = (__bfloat162float(th[tx][i]) + __bfloat162float(tl[tx][i])) * invv;
        bf16 h, l; split_bf16(v, h, l);
        oh[zo + (size_t)(c0 + i) * R + r0 + tx] = h;
        ol[zo + (size_t)(c0 + i) * R + r0 + tx] = l;
    }
}

// ---------------------------------------------------------------------------
__global__ void ln_split(const float* __restrict__ x, const float* __restrict__ g,
                         const float* __restrict__ b, bf16* __restrict__ yh,
                         bf16* __restrict__ yl, int D)
{
    const long row = blockIdx.x;
    const float* xr = x + row * D;

    float s = 0.f, s2 = 0.f;
    for (int i = threadIdx.x; i < D; i += blockDim.x) {
        float v = xr[i];
        s += v; s2 += v * v;
    }
#pragma unroll
    for (int o = 16; o; o >>= 1) {
        s  += __shfl_xor_sync(0xFFFFFFFFu, s,  o);
        s2 += __shfl_xor_sync(0xFFFFFFFFu, s2, o);
    }
    __shared__ float shs[8], shs2[8];
    __shared__ float mu_s, ri_s;
    const int w = threadIdx.x >> 5, l = threadIdx.x & 31;
    if (l == 0) { shs[w] = s; shs2[w] = s2; }
    __syncthreads();
    if (threadIdx.x == 0) {
        const int nw = blockDim.x >> 5;
        float ts = 0.f, ts2 = 0.f;
        for (int i = 0; i < nw; i++) { ts += shs[i]; ts2 += shs2[i]; }
        float mu  = ts / D;
        float var = ts2 / D - mu * mu;
        mu_s = mu;
        ri_s = rsqrtf(var + 1e-5f);
    }
    __syncthreads();
    const float mu = mu_s, ri = ri_s;
    for (int i = threadIdx.x; i < D; i += blockDim.x) {
        float v = (xr[i] - mu) * ri * g[i] + b[i];
        bf16 h, lo; split_bf16(v, h, lo);
        yh[row * D + i] = h;
        yl[row * D + i] = lo;
    }
}

// ---------------------------------------------------------------------------
__global__ void mlp2_reduce(const float* __restrict__ part, const float* __restrict__ b2,
                            float* __restrict__ out)
{
    const size_t P = (size_t)BB * TT * EE;
    const size_t i = (size_t)blockIdx.x * blockDim.x + threadIdx.x;
    const int n = (int)(i & (EE - 1));
    out[i] = part[i] + part[i + P] + part[i + 2 * P] + part[i + 3 * P] + b2[n];
}

// ---------------------------------------------------------------------------
extern "C" void kernel_launch(void* const* d_in, const int* in_sizes, int n_in,
                              void* d_out, int out_size)
{
    const float* X    = (const float*)d_in[0];
    const float* ln1g = (const float*)d_in[1];
    const float* ln1b = (const float*)d_in[2];
    const float* Wq   = (const float*)d_in[3];
    const float* bq   = (const float*)d_in[4];
    const float* Wk   = (const float*)d_in[5];
    const float* bk   = (const float*)d_in[6];
    const float* Wv   = (const float*)d_in[7];
    const float* bv   = (const float*)d_in[8];
    const float* ln2g = (const float*)d_in[9];
    const float* ln2b = (const float*)d_in[10];
    const float* W1   = (const float*)d_in[11];
    const float* b1   = (const float*)d_in[12];
    const float* W2   = (const float*)d_in[13];
    const float* b2   = (const float*)d_in[14];
    float* out = (float*)d_out;

    float *cc, *part, *psum, *inv;
    bf16 *Sh, *Sl, *Xnh, *Xnl, *qh, *ql, *kh, *kl, *vh, *vl, *vth, *vtl;
    bf16 *cch, *ccl, *midh, *midl;
    bf16 *Wqh, *Wql, *Wkh, *Wkl, *Wvh, *Wvl, *W1h, *W1l, *W2h, *W2l;
    cudaGetSymbolAddress((void**)&Sh,   g_Sh);
    cudaGetSymbolAddress((void**)&Sl,   g_Sl);
    cudaGetSymbolAddress((void**)&psum, g_psum);
    cudaGetSymbolAddress((void**)&inv,  g_inv);
    cudaGetSymbolAddress((void**)&Xnh,  g_Xnh);
    cudaGetSymbolAddress((void**)&Xnl,  g_Xnl);
    cudaGetSymbolAddress((void**)&qh,   g_qh);
    cudaGetSymbolAddress((void**)&ql,   g_ql);
    cudaGetSymbolAddress((void**)&kh,   g_kh);
    cudaGetSymbolAddress((void**)&kl,   g_kl);
    cudaGetSymbolAddress((void**)&vh,   g_vh);
    cudaGetSymbolAddress((void**)&vl,   g_vl);
    cudaGetSymbolAddress((void**)&vth,  g_vth);
    cudaGetSymbolAddress((void**)&vtl,  g_vtl);
    cudaGetSymbolAddress((void**)&cc,   g_cc);
    cudaGetSymbolAddress((void**)&cch,  g_cch);
    cudaGetSymbolAddress((void**)&ccl,  g_ccl);
    cudaGetSymbolAddress((void**)&midh, g_midh);
    cudaGetSymbolAddress((void**)&midl, g_midl);
    cudaGetSymbolAddress((void**)&Wqh,  g_Wqh);
    cudaGetSymbolAddress((void**)&Wql,  g_Wql);
    cudaGetSymbolAddress((void**)&Wkh,  g_Wkh);
    cudaGetSymbolAddress((void**)&Wkl,  g_Wkl);
    cudaGetSymbolAddress((void**)&Wvh,  g_Wvh);
    cudaGetSymbolAddress((void**)&Wvl,  g_Wvl);
    cudaGetSymbolAddress((void**)&W1h,  g_W1h);
    cudaGetSymbolAddress((void**)&W1l,  g_W1l);
    cudaGetSymbolAddress((void**)&W2h,  g_W2h);
    cudaGetSymbolAddress((void**)&W2l,  g_W2l);
    cudaGetSymbolAddress((void**)&part, g_part);

    const ZOff z0   = {1, 1, 0, 0};
    const ZOff oXn  = {HH, 1, (long)TT * EE, 0};
    const ZOff oWh  = {1, HH, 0, (long)EE * EE};
    const ZOff obh  = {1, HH, 0, (long)EE};
    const ZOff oQKV = {1, 1, (long)TT * EE, 0};
    const ZOff oS   = {1, 1, (long)TT * TT, 0};
    const ZOff oCC  = {HH, HH, (long)TT * DD, (long)EE};
    const ZOff oK1  = {1, 4, 0, 1024};
    const ZOff oP   = {1, 4, 0, (long)BB * TT * EE};

    const int SMEM = 2 * STAGE_ELEMS * (int)sizeof(bf16);   // 80 KB
    cudaFuncSetAttribute(gemm_bt<0, 0>, cudaFuncAttributeMaxDynamicSharedMemorySize, SMEM);
    cudaFuncSetAttribute(gemm_bt<0, 2>, cudaFuncAttributeMaxDynamicSharedMemorySize, SMEM);
    cudaFuncSetAttribute(gemm_bt<1, 0>, cudaFuncAttributeMaxDynamicSharedMemorySize, SMEM);
    cudaFuncSetAttribute(gemm_bt<2, 0>, cudaFuncAttributeMaxDynamicSharedMemorySize, SMEM);
    cudaFuncSetAttribute(gemm_bt<3, 1>, cudaFuncAttributeMaxDynamicSharedMemorySize, SMEM);

    dim3 tb(32, 8);

    // 0. one-time weight split+transpose
    split_tr<<<dim3(4, 4, HH), tb>>>(Wq, Wqh, Wql, EE, EE);
    split_tr<<<dim3(4, 4, HH), tb>>>(Wk, Wkh, Wkl, EE, EE);
    split_tr<<<dim3(4, 4, HH), tb>>>(Wv, Wvh, Wvl, EE, EE);
    split_tr<<<dim3(FF / 32, DD / 32, 1), tb>>>(W1, W1h, W1l, DD, FF);
    split_tr<<<dim3(EE / 32, FF / 32, 1), tb>>>(W2, W2h, W2l, FF, EE);

    // 1. LN1 -> Xn planes
    ln_split<<<BB * TT, 128>>>(X, ln1g, ln1b, Xnh, Xnl, EE);

    // 2. Q,K,V projections -> planes
    dim3 gqkv(1, TT / 128, BB * HH);
    gemm_bt<1, 0><<<gqkv, 256, SMEM>>>(Xnh, Xnl, Wqh, Wql, nullptr, qh, ql, bq, nullptr,
                                       TT, EE, EE, EE, EE, EE, 1.f, oXn, oWh, oQKV, obh);
    gemm_bt<1, 0><<<gqkv, 256, SMEM>>>(Xnh, Xnl, Wkh, Wkl, nullptr, kh, kl, bk, nullptr,
                                       TT, EE, EE, EE, EE, EE, 1.f, oXn, oWh, oQKV, obh);
    gemm_bt<1, 0><<<gqkv, 256, SMEM>>>(Xnh, Xnl, Wvh, Wvl, nullptr, vh, vl, bv, nullptr,
                                       TT, EE, EE, EE, EE, EE, 1.f, oXn, oWh, oQKV, obh);

    // 3. e = exp(Q@K^T/sqrt(E)) with causal zeroing, direct to planes + psums
    dim3 gsc(TT / 128, TT / 128, BB * HH);
    gemm_bt<3, 1><<<gsc, 256, SMEM>>>(qh, ql, kh, kl, nullptr, Sh, Sl, nullptr, psum,
                                      TT, TT, EE, EE, EE, TT,
                                      0.08838834764831845f, oQKV, oQKV, oS, z0);

    // 4. column sums -> inv ;  V transpose scaled by inv
    colsum_inv<<<dim3(TT / 256, BB * HH), 256>>>(psum, inv);
    tr_planes_scaled<<<dim3(EE / 32, TT / 32, BB * HH), tb>>>(vh, vl, inv, vth, vtl, TT, EE);

    // 5. cc = e @ (inv*V) (K truncated at diag block) -> f32 concat [B,T,D]
    dim3 gav(1, TT / 128, BB * HH);
    gemm_bt<0, 2><<<gav, 256, SMEM>>>(Sh, Sl, vth, vtl, cc, nullptr, nullptr, nullptr, nullptr,
                                      TT, EE, TT, TT, TT, DD, 1.f, oS, oQKV, oCC, z0);

    // 6. LN2 -> cc planes
    ln_split<<<BB * TT, 256>>>(cc, ln2g, ln2b, cch, ccl, DD);

    // 7. mid = gelu(cc @ W1 + b1) -> planes
    dim3 g1(FF / 128, (BB * TT) / 128, 1);
    gemm_bt<2, 0><<<g1, 256, SMEM>>>(cch, ccl, W1h, W1l, nullptr, midh, midl, b1, nullptr,
                                     BB * TT, FF, DD, DD, DD, FF, 1.f, z0, z0, z0, z0);

    // 8. out = mid @ W2 + b2 : split-K x4, then reduce
    dim3 g2(1, (BB * TT) / 128, 4);
    gemm_bt<0, 0><<<g2, 256, SMEM>>>(midh, midl, W2h, W2l, part, nullptr, nullptr, nullptr, nullptr,
                                     BB * TT, EE, 1024, FF, FF, EE, 1.f, oK1, oK1, oP, z0);
    mlp2_reduce<<<(BB * TT * EE) / 256, 256>>>(part, b2, out);
}

// round 11
// speedup vs baseline: 3.7975x; 1.0333x over previous
#include <cuda_runtime.h>
#include <cuda_bf16.h>
#include <math.h>
#include <stdint.h>

#define BB 4
#define TT 2048
#define EE 128
#define HH 8
#define DD 1024
#define FF 4096

typedef __nv_bfloat16 bf16;

// ---------------------------------------------------------------------------
// Scratch (static device globals; no allocation anywhere)
// ---------------------------------------------------------------------------
__device__ bf16  g_Sh [(size_t)BB*HH*TT*TT];          // attn e hi plane
__device__ bf16  g_Sl [(size_t)BB*HH*TT*TT];          // attn e lo plane
__device__ float g_psum[(size_t)BB*HH*(TT/128)*TT];   // per-mblock column sums
__device__ float g_inv [(size_t)BB*HH*TT];            // 1/colsum
__device__ bf16  g_Xnh[(size_t)BB*TT*EE], g_Xnl[(size_t)BB*TT*EE];
__device__ bf16  g_qh [(size_t)BB*HH*TT*EE], g_ql [(size_t)BB*HH*TT*EE];
__device__ bf16  g_kh [(size_t)BB*HH*TT*EE], g_kl [(size_t)BB*HH*TT*EE];
__device__ bf16  g_vh [(size_t)BB*HH*TT*EE], g_vl [(size_t)BB*HH*TT*EE];
__device__ bf16  g_vth[(size_t)BB*HH*TT*EE], g_vtl[(size_t)BB*HH*TT*EE];
__device__ float g_cc [(size_t)BB*TT*DD];
__device__ bf16  g_cch[(size_t)BB*TT*DD], g_ccl[(size_t)BB*TT*DD];
__device__ bf16  g_midh[(size_t)BB*TT*FF], g_midl[(size_t)BB*TT*FF];
__device__ bf16  g_Wqh[(size_t)HH*EE*EE], g_Wql[(size_t)HH*EE*EE];
__device__ bf16  g_Wkh[(size_t)HH*EE*EE], g_Wkl[(size_t)HH*EE*EE];
__device__ bf16  g_Wvh[(size_t)HH*EE*EE], g_Wvl[(size_t)HH*EE*EE];
__device__ bf16  g_W1h[(size_t)DD*FF],   g_W1l[(size_t)DD*FF];   // [F][D]
__device__ bf16  g_W2h[(size_t)FF*EE],   g_W2l[(size_t)FF*EE];   // [E][F]
__device__ float g_part[(size_t)4*BB*TT*EE];                      // MLP2 split-K
__device__ float g_partA[(size_t)4*BB*HH*TT*EE];                  // attnV split-K

// ---------------------------------------------------------------------------
struct ZOff { int dv; int md; long sd; long sm; };
__device__ __forceinline__ long zoff(ZOff o, int z) {
    return (long)(z / o.dv) * o.sd + (long)(z % o.md) * o.sm;
}

// pointer bundle for the fused QKV launch
struct QKVP {
    const bf16* wh[3]; const bf16* wl[3];
    const float* bias[3];
    bf16* oh[3]; bf16* ol[3];
};

__device__ __forceinline__ void split_bf16(float x, bf16& h, bf16& l) {
    h = __float2bfloat16(x);
    l = __float2bfloat16(x - __bfloat162float(h));
}
__device__ __forceinline__ uint32_t pack2(bf16 a, bf16 b) {
    uint32_t ua = __bfloat16_as_ushort(a), ub = __bfloat16_as_ushort(b);
    return ua | (ub << 16);
}

__device__ __forceinline__ void mma_bf16(float* c,
                                         const uint32_t* a, uint32_t b0, uint32_t b1) {
    asm volatile(
        "mma.sync.aligned.m16n8k16.row.col.f32.bf16.bf16.f32 "
        "{%0,%1,%2,%3}, {%4,%5,%6,%7}, {%8,%9}, {%0,%1,%2,%3};"
        : "+f"(c[0]), "+f"(c[1]), "+f"(c[2]), "+f"(c[3])
        : "r"(a[0]), "r"(a[1]), "r"(a[2]), "r"(a[3]), "r"(b0), "r"(b1));
}

__device__ __forceinline__ void ldsm4(uint32_t* r, const bf16* p) {
    uint32_t a = (uint32_t)__cvta_generic_to_shared(p);
    asm volatile("ldmatrix.sync.aligned.m8n8.x4.shared.b16 {%0,%1,%2,%3}, [%4];"
        : "=r"(r[0]), "=r"(r[1]), "=r"(r[2]), "=r"(r[3]) : "r"(a));
}

__device__ __forceinline__ void cpa16(bf16* smem, const bf16* gmem) {
    uint32_t s = (uint32_t)__cvta_generic_to_shared(smem);
    asm volatile("cp.async.cg.shared.global [%0], [%1], 16;" :: "r"(s), "l"(gmem));
}

// SMEM stage layout (bf16 elems): Ah[0,5120) Al[5120,..) Bh[10240,..) Bl[15360,..)
// row stride 40. Two stages = 80 KB dynamic SMEM.
#define STAGE_ELEMS 20480
#define ROWS_LD 40

// ---------------------------------------------------------------------------
// GEMM on pre-split bf16 hi/lo planes. C = act(scale * A @ B^T + bias)
//   EPI   : 0 f32*scale -> Cf ; 1 split+bias -> planes ; 2 +gelu -> planes
//           3 exp(scale*acc), causal zero (m<n), -> planes + column psums
//   CMODE : 0 normal; 1 skip blocks above diagonal;
//           3 attnV split-K (z = hb*4+slice, 512-wide K windows, f32 partials)
//           4 fused QKV (z = proj*BH+hb, pointers from QKVP)
// ---------------------------------------------------------------------------
template <int EPI, int CMODE>
__global__ __launch_bounds__(256, 2) void gemm_bt(
    const bf16* __restrict__ Ahg, const bf16* __restrict__ Alg,
    const bf16* __restrict__ Bhg, const bf16* __restrict__ Blg,
    float* __restrict__ Cf, bf16* __restrict__ Chg, bf16* __restrict__ Clg,
    const float* __restrict__ bias, float* __restrict__ psum,
    int M, int N, int K, int lda, int ldb, int ldc, float scale,
    ZOff oa, ZOff ob, ZOff oc, ZOff obias, QKVP qp)
{
    const int z = blockIdx.z;
    const int n0 = blockIdx.x * 128;
    const int m0 = blockIdx.y * 128;

    int it0 = 0, itEnd;

    if (CMODE == 4) {
        const int proj = z / (BB * HH);
        const int hb   = z % (BB * HH);
        const long ao = (long)(hb / HH) * TT * EE;
        Ahg += ao; Alg += ao;
        Bhg = qp.wh[proj] + (long)(hb % HH) * EE * EE;
        Blg = qp.wl[proj] + (long)(hb % HH) * EE * EE;
        Chg = qp.oh[proj] + (long)hb * TT * EE;
        Clg = qp.ol[proj] + (long)hb * TT * EE;
        bias = qp.bias[proj] + (hb % HH) * EE;
        itEnd = K >> 5;
    } else if (CMODE == 3) {
        const int hb = z >> 2, slice = z & 3;
        Ahg += (long)hb * TT * TT; Alg += (long)hb * TT * TT;
        Bhg += (long)hb * TT * EE; Blg += (long)hb * TT * EE;
        Cf  += (long)z * TT * EE;                       // partial plane
        const int kB = slice * 512;
        const int kE = min(m0 + 128, kB + 512);
        if (kB >= kE) return;
        it0 = kB >> 5;
        itEnd = kE >> 5;
    } else {
        const long za = zoff(oa, z), zb = zoff(ob, z), zc = zoff(oc, z);
        Ahg += za; Alg += za;
        Bhg += zb; Blg += zb;
        if (EPI == 0) Cf += zc; else { Chg += zc; Clg += zc; }
        if (EPI == 1 || EPI == 2) bias += zoff(obias, z);
        if (CMODE == 1 && m0 < n0) return;
        itEnd = K >> 5;
    }

    extern __shared__ bf16 dyn[];
    __shared__ float scol[8][128];

    const int tid  = threadIdx.x;
    const int lane = tid & 31;
    const int wid  = tid >> 5;
    const int wm   = wid & 3;
    const int wn   = wid >> 2;

    float acc[2][8][4];
#pragma unroll
    for (int i = 0; i < 2; i++)
#pragma unroll
        for (int j = 0; j < 8; j++)
#pragma unroll
            for (int r = 0; r < 4; r++) acc[i][j][r] = 0.f;

    // cp.async loaders
    const int lr = tid >> 1;
    const int lc = (tid & 1) * 16;
    const bf16* Agh = Ahg + (size_t)(m0 + lr) * lda + lc;
    const bf16* Agl = Alg + (size_t)(m0 + lr) * lda + lc;
    const bf16* Bgh = Bhg + (size_t)(n0 + lr) * ldb + lc;
    const bf16* Bgl = Blg + (size_t)(n0 + lr) * ldb + lc;
    const int ldst = lr * ROWS_LD + lc;

    // ldmatrix per-lane offsets (non-trans; operands stored [row][k])
    const int m8 = lane >> 3, r8 = lane & 7;
    const int aoff = (wm * 32 + (m8 & 1) * 8 + r8) * ROWS_LD + (m8 >> 1) * 8;
    const int boff = (wn * 64 + (m8 >> 1) * 8 + r8) * ROWS_LD + (m8 & 1) * 8;

#define ISSUE(it, buf)                                                        \
    do {                                                                      \
        bf16* st = dyn + (buf) * STAGE_ELEMS;                                 \
        const int ko = (it) << 5;                                             \
        cpa16(st + ldst,         Agh + ko); cpa16(st + ldst + 8,         Agh + ko + 8); \
        cpa16(st + 5120 + ldst,  Agl + ko); cpa16(st + 5120 + ldst + 8,  Agl + ko + 8); \
        cpa16(st + 10240 + ldst, Bgh + ko); cpa16(st + 10240 + ldst + 8, Bgh + ko + 8); \
        cpa16(st + 15360 + ldst, Bgl + ko); cpa16(st + 15360 + ldst + 8, Bgl + ko + 8); \
        asm volatile("cp.async.commit_group;");                               \
    } while (0)

    ISSUE(it0, 0);

    for (int it = it0, r = 0; it < itEnd; ++it, ++r) {
        if (it + 1 < itEnd) {
            ISSUE(it + 1, (r + 1) & 1);
            asm volatile("cp.async.wait_group 1;" ::: "memory");
        } else {
            asm volatile("cp.async.wait_group 0;" ::: "memory");
        }
        __syncthreads();

        const bf16* st = dyn + (r & 1) * STAGE_ELEMS;
        const bf16* sAh = st;
        const bf16* sAl = st + 5120;
        const bf16* sBh = st + 10240;
        const bf16* sBl = st + 15360;

#pragma unroll
        for (int s = 0; s < 2; s++) {
            const int kk = s * 16;
            uint32_t ah[2][4], al[2][4];
            ldsm4(ah[0], sAh + aoff + kk);
            ldsm4(ah[1], sAh + aoff + 640 + kk);
            ldsm4(al[0], sAl + aoff + kk);
            ldsm4(al[1], sAl + aoff + 640 + kk);
#pragma unroll
            for (int ntp = 0; ntp < 4; ntp++) {
                uint32_t bh[4], bl[4];
                ldsm4(bh, sBh + boff + ntp * 640 + kk);
                ldsm4(bl, sBl + boff + ntp * 640 + kk);
#pragma unroll
                for (int j = 0; j < 2; j++) {
#pragma unroll
                    for (int mt = 0; mt < 2; mt++) {
                        float* c = acc[mt][2 * ntp + j];
                        mma_bf16(c, ah[mt], bh[2 * j], bh[2 * j + 1]);
                        mma_bf16(c, ah[mt], bl[2 * j], bl[2 * j + 1]);
                        mma_bf16(c, al[mt], bh[2 * j], bh[2 * j + 1]);
                    }
                }
            }
        }
        __syncthreads();
    }
#undef ISSUE

    // ---------------- epilogue ----------------
#pragma unroll
    for (int mt = 0; mt < 2; mt++) {
#pragma unroll
        for (int nt = 0; nt < 8; nt++) {
            const int r0 = m0 + wm * 32 + mt * 16 + (lane >> 2);
            const int cb = n0 + wn * 64 + nt * 8 + (lane & 3) * 2;
            float v[4];
#pragma unroll
            for (int r = 0; r < 4; r++) v[r] = acc[mt][nt][r] * scale;
            if (EPI == 1 || EPI == 2) {
                float b0 = bias[cb], b1 = bias[cb + 1];
                v[0] += b0; v[1] += b1; v[2] += b0; v[3] += b1;
            }
            if (EPI == 2) {
#pragma unroll
                for (int r = 0; r < 4; r++)
                    v[r] = 0.5f * v[r] * (1.0f + erff(v[r] * 0.70710678118654752f));
            }
            if (EPI == 3) {
                v[0] = (r0 < cb)         ? 0.f : __expf(v[0]);
                v[1] = (r0 < cb + 1)     ? 0.f : __expf(v[1]);
                v[2] = (r0 + 8 < cb)     ? 0.f : __expf(v[2]);
                v[3] = (r0 + 8 < cb + 1) ? 0.f : __expf(v[3]);
                float s0 = v[0] + v[2], s1 = v[1] + v[3];
#pragma unroll
                for (int o = 4; o < 32; o <<= 1) {
                    s0 += __shfl_xor_sync(0xFFFFFFFFu, s0, o);
                    s1 += __shfl_xor_sync(0xFFFFFFFFu, s1, o);
                }
                if (lane < 4) {
                    scol[wm * 2 + mt][wn * 64 + nt * 8 + lane * 2]     = s0;
                    scol[wm * 2 + mt][wn * 64 + nt * 8 + lane * 2 + 1] = s1;
                }
            }
            if (EPI == 0) {
                *(float2*)&Cf[(size_t)r0 * ldc + cb]       = make_float2(v[0], v[1]);
                *(float2*)&Cf[(size_t)(r0 + 8) * ldc + cb] = make_float2(v[2], v[3]);
            } else {
                bf16 h0, l0, h1, l1;
                split_bf16(v[0], h0, l0); split_bf16(v[1], h1, l1);
                *(uint32_t*)&Chg[(size_t)r0 * ldc + cb] = pack2(h0, h1);
                *(uint32_t*)&Clg[(size_t)r0 * ldc + cb] = pack2(l0, l1);
                split_bf16(v[2], h0, l0); split_bf16(v[3], h1, l1);
                *(uint32_t*)&Chg[(size_t)(r0 + 8) * ldc + cb] = pack2(h0, h1);
                *(uint32_t*)&Clg[(size_t)(r0 + 8) * ldc + cb] = pack2(l0, l1);
            }
        }
    }

    if (EPI == 3) {
        __syncthreads();
        if (tid < 128) {
            float p = 0.f;
#pragma unroll
            for (int sl = 0; sl < 8; sl++) p += scol[sl][tid];
            psum[((size_t)z * (TT / 128) + blockIdx.y) * TT + n0 + tid] = p;
        }
    }
}

// ---------------------------------------------------------------------------
// inv[s] = 1 / sum over valid m-blocks of psum
// ---------------------------------------------------------------------------
__global__ void colsum_inv(const float* __restrict__ psum, float* __restrict__ inv)
{
    const int s = blockIdx.x * blockDim.x + threadIdx.x;
    const int z = blockIdx.y;
    float sum = 0.f;
    for (int mb = s >> 7; mb < TT / 128; mb++)
        sum += psum[((size_t)z * (TT / 128) + mb) * TT + s];
    inv[(size_t)z * TT + s] = 1.f / sum;
}

// ---------------------------------------------------------------------------
// attnV split-K reduce: cc[b][t][h*E+e] = sum over valid slices of partials
// ---------------------------------------------------------------------------
__global__ void attn_reduce(const float* __restrict__ part, float* __restrict__ cc)
{
    const size_t i = (size_t)blockIdx.x * blockDim.x + threadIdx.x;
    const int e  = (int)(i & (EE - 1));
    const int t  = (int)((i >> 7) & (TT - 1));
    const int hb = (int)(i >> 18);
    const int b = hb >> 3, h = hb & 7;
    const int nsl = (((t >> 7) + 1) * 128 + 511) >> 9;
    const float* p = part + ((size_t)hb * 4) * TT * EE + (size_t)t * EE + e;
    float s = 0.f;
    for (int sl = 0; sl < nsl; sl++) s += p[(size_t)sl * TT * EE];
    cc[(size_t)b * TT * DD + (size_t)t * DD + h * EE + e] = s;
}

// ---------------------------------------------------------------------------
__global__ void split_tr(const float* __restrict__ src, bf16* __restrict__ oh,
                         bf16* __restrict__ ol, int R, int C)
{
    __shared__ float t[32][33];
    const size_t zo = (size_t)blockIdx.z * R * C;
    const int c0 = blockIdx.x * 32, r0 = blockIdx.y * 32;
    const int tx = threadIdx.x, ty = threadIdx.y;
    for (int i = ty; i < 32; i += 8)
        t[i][tx] = src[zo + (size_t)(r0 + i) * C + c0 + tx];
    __syncthreads();
    for (int i = ty; i < 32; i += 8) {
        float v = t[tx][i];
        bf16 h, l; split_bf16(v, h, l);
        oh[zo + (size_t)(c0 + i) * R + r0 + tx] = h;
        ol[zo + (size_t)(c0 + i) * R + r0 + tx] = l;
    }
}

// Transpose V planes [T][E] -> [E][T], scaling row t by inv[t] (fp32 combine).
__global__ void tr_planes_scaled(const bf16* __restrict__ ih, const bf16* __restrict__ il,
                                 const float* __restrict__ inv,
                                 bf16* __restrict__ oh, bf16* __restrict__ ol,
                                 int R, int C)
{
    __shared__ bf16 th[32][33], tl[32][33];
    const size_t zo = (size_t)blockIdx.z * R * C;
    const int c0 = blockIdx.x * 32, r0 = blockIdx.y * 32;
    const int tx = threadIdx.x, ty = threadIdx.y;
    for (int i = ty; i < 32; i += 8) {
        th[i][tx] = ih[zo + (size_t)(r0 + i) * C + c0 + tx];
        tl[i][tx] = il[zo + (size_t)(r0 + i) * C + c0 + tx];
    }
    __syncthreads();
    const float invv = inv[(size_t)blockIdx.z * R + r0 + tx];
    for (int i = ty; i < 32; i += 8) {
        float v = (__bfloat162float(th[tx][i]) + __bfloat162float(tl[tx][i])) * invv;
        bf16 h, l; split_bf16(v, h, l);
        oh[zo + (size_t)(c0 + i) * R + r0 + tx] = h;
        ol[zo + (size_t)(c0 + i) * R + r0 + tx] = l;
    }
}

// ---------------------------------------------------------------------------
__global__ void ln_split(const float* __restrict__ x, const float* __restrict__ g,
                         const float* __restrict__ b, bf16* __restrict__ yh,
                         bf16* __restrict__ yl, int D)
{
    const long row = blockIdx.x;
    const float* xr = x + row * D;

    float s = 0.f, s2 = 0.f;
    for (int i = threadIdx.x; i < D; i += blockDim.x) {
        float v = xr[i];
        s += v; s2 += v * v;
    }
#pragma unroll
    for (int o = 16; o; o >>= 1) {
        s  += __shfl_xor_sync(0xFFFFFFFFu, s,  o);
        s2 += __shfl_xor_sync(0xFFFFFFFFu, s2, o);
    }
    __shared__ float shs[8], shs2[8];
    __shared__ float mu_s, ri_s;
    const int w = threadIdx.x >> 5, l = threadIdx.x & 31;
    if (l == 0) { shs[w] = s; shs2[w] = s2; }
    __syncthreads();
    if (threadIdx.x == 0) {
        const int nw = blockDim.x >> 5;
        float ts = 0.f, ts2 = 0.f;
        for (int i = 0; i < nw; i++) { ts += shs[i]; ts2 += shs2[i]; }
        float mu  = ts / D;
        float var = ts2 / D - mu * mu;
        mu_s = mu;
        ri_s = rsqrtf(var + 1e-5f);
    }
    __syncthreads();
    const float mu = mu_s, ri = ri_s;
    for (int i = threadIdx.x; i < D; i += blockDim.x) {
        float v = (xr[i] - mu) * ri * g[i] + b[i];
        bf16 h, lo; split_bf16(v, h, lo);
        yh[row * D + i] = h;
        yl[row * D + i] = lo;
    }
}

// ---------------------------------------------------------------------------
__global__ void mlp2_reduce(const float* __restrict__ part, const float* __restrict__ b2,
                            float* __restrict__ out)
{
    const size_t P = (size_t)BB * TT * EE;
    const size_t i = (size_t)blockIdx.x * blockDim.x + threadIdx.x;
    const int n = (int)(i & (EE - 1));
    out[i] = part[i] + part[i + P] + part[i + 2 * P] + part[i + 3 * P] + b2[n];
}

// ---------------------------------------------------------------------------
extern "C" void kernel_launch(void* const* d_in, const int* in_sizes, int n_in,
                              void* d_out, int out_size)
{
    const float* X    = (const float*)d_in[0];
    const float* ln1g = (const float*)d_in[1];
    const float* ln1b = (const float*)d_in[2];
    const float* Wq   = (const float*)d_in[3];
    const float* bq   = (const float*)d_in[4];
    const float* Wk   = (const float*)d_in[5];
    const float* bk   = (const float*)d_in[6];
    const float* Wv   = (const float*)d_in[7];
    const float* bv   = (const float*)d_in[8];
    const float* ln2g = (const float*)d_in[9];
    const float* ln2b = (const float*)d_in[10];
    const float* W1   = (const float*)d_in[11];
    const float* b1   = (const float*)d_in[12];
    const float* W2   = (const float*)d_in[13];
    const float* b2   = (const float*)d_in[14];
    float* out = (float*)d_out;

    float *cc, *part, *partA, *psum, *inv;
    bf16 *Sh, *Sl, *Xnh, *Xnl, *qh, *ql, *kh, *kl, *vh, *vl, *vth, *vtl;
    bf16 *cch, *ccl, *midh, *midl;
    bf16 *Wqh, *Wql, *Wkh, *Wkl, *Wvh, *Wvl, *W1h, *W1l, *W2h, *W2l;
    cudaGetSymbolAddress((void**)&Sh,   g_Sh);
    cudaGetSymbolAddress((void**)&Sl,   g_Sl);
    cudaGetSymbolAddress((void**)&psum, g_psum);
    cudaGetSymbolAddress((void**)&inv,  g_inv);
    cudaGetSymbolAddress((void**)&Xnh,  g_Xnh);
    cudaGetSymbolAddress((void**)&Xnl,  g_Xnl);
    cudaGetSymbolAddress((void**)&qh,   g_qh);
    cudaGetSymbolAddress((void**)&ql,   g_ql);
    cudaGetSymbolAddress((void**)&kh,   g_kh);
    cudaGetSymbolAddress((void**)&kl,   g_kl);
    cudaGetSymbolAddress((void**)&vh,   g_vh);
    cudaGetSymbolAddress((void**)&vl,   g_vl);
    cudaGetSymbolAddress((void**)&vth,  g_vth);
    cudaGetSymbolAddress((void**)&vtl,  g_vtl);
    cudaGetSymbolAddress((void**)&cc,   g_cc);
    cudaGetSymbolAddress((void**)&cch,  g_cch);
    cudaGetSymbolAddress((void**)&ccl,  g_ccl);
    cudaGetSymbolAddress((void**)&midh, g_midh);
    cudaGetSymbolAddress((void**)&midl, g_midl);
    cudaGetSymbolAddress((void**)&Wqh,  g_Wqh);
    cudaGetSymbolAddress((void**)&Wql,  g_Wql);
    cudaGetSymbolAddress((void**)&Wkh,  g_Wkh);
    cudaGetSymbolAddress((void**)&Wkl,  g_Wkl);
    cudaGetSymbolAddress((void**)&Wvh,  g_Wvh);
    cudaGetSymbolAddress((void**)&Wvl,  g_Wvl);
    cudaGetSymbolAddress((void**)&W1h,  g_W1h);
    cudaGetSymbolAddress((void**)&W1l,  g_W1l);
    cudaGetSymbolAddress((void**)&W2h,  g_W2h);
    cudaGetSymbolAddress((void**)&W2l,  g_W2l);
    cudaGetSymbolAddress((void**)&part, g_part);
    cudaGetSymbolAddress((void**)&partA, g_partA);

    const ZOff z0   = {1, 1, 0, 0};
    const ZOff oQKV = {1, 1, (long)TT * EE, 0};
    const ZOff oS   = {1, 1, (long)TT * TT, 0};
    const ZOff oK1  = {1, 4, 0, 1024};
    const ZOff oP   = {1, 4, 0, (long)BB * TT * EE};

    QKVP qp{};
    qp.wh[0] = Wqh; qp.wh[1] = Wkh; qp.wh[2] = Wvh;
    qp.wl[0] = Wql; qp.wl[1] = Wkl; qp.wl[2] = Wvl;
    qp.bias[0] = bq; qp.bias[1] = bk; qp.bias[2] = bv;
    qp.oh[0] = qh; qp.oh[1] = kh; qp.oh[2] = vh;
    qp.ol[0] = ql; qp.ol[1] = kl; qp.ol[2] = vl;
    QKVP qdummy{};

    const int SMEM = 2 * STAGE_ELEMS * (int)sizeof(bf16);   // 80 KB
    cudaFuncSetAttribute(gemm_bt<0, 0>, cudaFuncAttributeMaxDynamicSharedMemorySize, SMEM);
    cudaFuncSetAttribute(gemm_bt<0, 3>, cudaFuncAttributeMaxDynamicSharedMemorySize, SMEM);
    cudaFuncSetAttribute(gemm_bt<1, 4>, cudaFuncAttributeMaxDynamicSharedMemorySize, SMEM);
    cudaFuncSetAttribute(gemm_bt<2, 0>, cudaFuncAttributeMaxDynamicSharedMemorySize, SMEM);
    cudaFuncSetAttribute(gemm_bt<3, 1>, cudaFuncAttributeMaxDynamicSharedMemorySize, SMEM);

    dim3 tb(32, 8);

    // 0. one-time weight split+transpose
    split_tr<<<dim3(4, 4, HH), tb>>>(Wq, Wqh, Wql, EE, EE);
    split_tr<<<dim3(4, 4, HH), tb>>>(Wk, Wkh, Wkl, EE, EE);
    split_tr<<<dim3(4, 4, HH), tb>>>(Wv, Wvh, Wvl, EE, EE);
    split_tr<<<dim3(FF / 32, DD / 32, 1), tb>>>(W1, W1h, W1l, DD, FF);
    split_tr<<<dim3(EE / 32, FF / 32, 1), tb>>>(W2, W2h, W2l, FF, EE);

    // 1. LN1 -> Xn planes
    ln_split<<<BB * TT, 128>>>(X, ln1g, ln1b, Xnh, Xnl, EE);

    // 2. fused QKV projections (z = proj*BH + hb) -> planes
    dim3 gqkv(1, TT / 128, 3 * BB * HH);
    gemm_bt<1, 4><<<gqkv, 256, SMEM>>>(Xnh, Xnl, nullptr, nullptr, nullptr, nullptr, nullptr,
                                       nullptr, nullptr,
                                       TT, EE, EE, EE, EE, EE, 1.f, z0, z0, z0, z0, qp);

    // 3. e = exp(Q@K^T/sqrt(E)) with causal zeroing, direct to planes + psums
    dim3 gsc(TT / 128, TT / 128, BB * HH);
    gemm_bt<3, 1><<<gsc, 256, SMEM>>>(qh, ql, kh, kl, nullptr, Sh, Sl, nullptr, psum,
                                      TT, TT, EE, EE, EE, TT,
                                      0.08838834764831845f, oQKV, oQKV, oS, z0, qdummy);

    // 4. column sums -> inv ;  V transpose scaled by inv
    colsum_inv<<<dim3(TT / 256, BB * HH), 256>>>(psum, inv);
    tr_planes_scaled<<<dim3(EE / 32, TT / 32, BB * HH), tb>>>(vh, vl, inv, vth, vtl, TT, EE);

    // 5. attnV split-K (z = hb*4+slice) -> f32 partials, then reduce into cc
    dim3 gav(1, TT / 128, BB * HH * 4);
    gemm_bt<0, 3><<<gav, 256, SMEM>>>(Sh, Sl, vth, vtl, partA, nullptr, nullptr, nullptr, nullptr,
                                      TT, EE, TT, TT, TT, EE, 1.f, z0, z0, z0, z0, qdummy);
    attn_reduce<<<(BB * HH * TT * EE) / 256, 256>>>(partA, cc);

    // 6. LN2 -> cc planes
    ln_split<<<BB * TT, 256>>>(cc, ln2g, ln2b, cch, ccl, DD);

    // 7. mid = gelu(cc @ W1 + b1) -> planes
    dim3 g1(FF / 128, (BB * TT) / 128, 1);
    gemm_bt<2, 0><<<g1, 256, SMEM>>>(cch, ccl, W1h, W1l, nullptr, midh, midl, b1, nullptr,
                                     BB * TT, FF, DD, DD, DD, FF, 1.f, z0, z0, z0, z0, qdummy);

    // 8. out = mid @ W2 + b2 : split-K x4, then reduce
    dim3 g2(1, (BB * TT) / 128, 4);
    gemm_bt<0, 0><<<g2, 256, SMEM>>>(midh, midl, W2h, W2l, part, nullptr, nullptr, nullptr, nullptr,
                                     BB * TT, EE, 1024, FF, FF, EE, 1.f, oK1, oK1, oP, z0, qdummy);
    mlp2_reduce<<<(BB * TT * EE) / 256, 256>>>(part, b2, out);
}

// round 13
// speedup vs baseline: 3.8077x; 1.0027x over previous
#include <cuda_runtime.h>
#include <cuda_bf16.h>
#include <math.h>
#include <stdint.h>

#define BB 4
#define TT 2048
#define EE 128
#define HH 8
#define DD 1024
#define FF 4096

typedef __nv_bfloat16 bf16;

// ---------------------------------------------------------------------------
// Scratch (static device globals; no allocation anywhere)
// ---------------------------------------------------------------------------
__device__ bf16  g_Sh [(size_t)BB*HH*TT*TT];
__device__ bf16  g_Sl [(size_t)BB*HH*TT*TT];
__device__ float g_psum[(size_t)BB*HH*(TT/128)*TT];
__device__ float g_inv [(size_t)BB*HH*TT];
__device__ bf16  g_Xnh[(size_t)BB*TT*EE], g_Xnl[(size_t)BB*TT*EE];
__device__ bf16  g_qh [(size_t)BB*HH*TT*EE], g_ql [(size_t)BB*HH*TT*EE];
__device__ bf16  g_kh [(size_t)BB*HH*TT*EE], g_kl [(size_t)BB*HH*TT*EE];
__device__ bf16  g_vh [(size_t)BB*HH*TT*EE], g_vl [(size_t)BB*HH*TT*EE];
__device__ bf16  g_vth[(size_t)BB*HH*TT*EE], g_vtl[(size_t)BB*HH*TT*EE];
__device__ float g_cc [(size_t)BB*TT*DD];
__device__ bf16  g_cch[(size_t)BB*TT*DD], g_ccl[(size_t)BB*TT*DD];
__device__ bf16  g_midh[(size_t)BB*TT*FF], g_midl[(size_t)BB*TT*FF];
__device__ bf16  g_Wqh[(size_t)HH*EE*EE], g_Wql[(size_t)HH*EE*EE];
__device__ bf16  g_Wkh[(size_t)HH*EE*EE], g_Wkl[(size_t)HH*EE*EE];
__device__ bf16  g_Wvh[(size_t)HH*EE*EE], g_Wvl[(size_t)HH*EE*EE];
__device__ bf16  g_W1h[(size_t)DD*FF],   g_W1l[(size_t)DD*FF];   // [F][D]
__device__ bf16  g_W2h[(size_t)FF*EE],   g_W2l[(size_t)FF*EE];   // [E][F]
__device__ float g_part[(size_t)4*BB*TT*EE];
__device__ float g_partA[(size_t)4*BB*HH*TT*EE];

// ---------------------------------------------------------------------------
struct ZOff { int dv; int md; long sd; long sm; };
__device__ __forceinline__ long zoff(ZOff o, int z) {
    return (long)(z / o.dv) * o.sd + (long)(z % o.md) * o.sm;
}
struct QKVP {
    const bf16* wh[3]; const bf16* wl[3];
    const float* bias[3];
    bf16* oh[3]; bf16* ol[3];
};

__device__ __forceinline__ void split_bf16(float x, bf16& h, bf16& l) {
    h = __float2bfloat16(x);
    l = __float2bfloat16(x - __bfloat162float(h));
}
__device__ __forceinline__ uint32_t pack2(bf16 a, bf16 b) {
    uint32_t ua = __bfloat16_as_ushort(a), ub = __bfloat16_as_ushort(b);
    return ua | (ub << 16);
}
__device__ __forceinline__ void mma_bf16(float* c,
                                         const uint32_t* a, uint32_t b0, uint32_t b1) {
    asm volatile(
        "mma.sync.aligned.m16n8k16.row.col.f32.bf16.bf16.f32 "
        "{%0,%1,%2,%3}, {%4,%5,%6,%7}, {%8,%9}, {%0,%1,%2,%3};"
        : "+f"(c[0]), "+f"(c[1]), "+f"(c[2]), "+f"(c[3])
        : "r"(a[0]), "r"(a[1]), "r"(a[2]), "r"(a[3]), "r"(b0), "r"(b1));
}
__device__ __forceinline__ void ldsm4(uint32_t* r, const bf16* p) {
    uint32_t a = (uint32_t)__cvta_generic_to_shared(p);
    asm volatile("ldmatrix.sync.aligned.m8n8.x4.shared.b16 {%0,%1,%2,%3}, [%4];"
        : "=r"(r[0]), "=r"(r[1]), "=r"(r[2]), "=r"(r[3]) : "r"(a));
}
__device__ __forceinline__ void cpa16(bf16* smem, const bf16* gmem) {
    uint32_t s = (uint32_t)__cvta_generic_to_shared(smem);
    asm volatile("cp.async.cg.shared.global [%0], [%1], 16;" :: "r"(s), "l"(gmem));
}

// SMEM stage layout (bf16 elems): Ah[0,5120) Al[5120,..) Bh[10240,..) Bl[15360,..)
// row stride 40. Two stages = 80 KB dynamic SMEM.
#define STAGE_ELEMS 20480
#define ROWS_LD 40

// ---------------------------------------------------------------------------
// GEMM on pre-split bf16 hi/lo planes. C = act(scale * A @ B^T + bias)
//   EPI   : 0 f32*scale -> Cf ; 1 split+bias -> planes ; 2 +gelu -> planes
//           3 exp(scale*acc), causal zero (m<n), -> planes + column psums
//   CMODE : 0 normal; 1 skip blocks above diagonal;
//           3 attnV split-K (z = hb*4+slice, 512-wide K windows, f32 partials)
//           4 fused QKV (z = proj*BH+hb, pointers from QKVP)
// Inner loop is combo-outermost: per B-tile, issue hh over all 4 accumulators,
// then hl, then lh -> same-accumulator HMMA reuse distance 4 (was 1), hiding
// the HMMA RAW latency. Per-accumulator addition order is unchanged (hh,hl,lh
// per k-step) so results are bit-identical to the previous version.
// ---------------------------------------------------------------------------
template <int EPI, int CMODE>
__global__ __launch_bounds__(256, 2) void gemm_bt(
    const bf16* __restrict__ Ahg, const bf16* __restrict__ Alg,
    const bf16* __restrict__ Bhg, const bf16* __restrict__ Blg,
    float* __restrict__ Cf, bf16* __restrict__ Chg, bf16* __restrict__ Clg,
    const float* __restrict__ bias, float* __restrict__ psum,
    int M, int N, int K, int lda, int ldb, int ldc, float scale,
    ZOff oa, ZOff ob, ZOff oc, ZOff obias, QKVP qp)
{
    const int z = blockIdx.z;
    const int n0 = blockIdx.x * 128;
    const int m0 = blockIdx.y * 128;

    int it0 = 0, itEnd;

    if (CMODE == 4) {
        const int proj = z / (BB * HH);
        const int hb   = z % (BB * HH);
        const long ao = (long)(hb / HH) * TT * EE;
        Ahg += ao; Alg += ao;
        Bhg = qp.wh[proj] + (long)(hb % HH) * EE * EE;
        Blg = qp.wl[proj] + (long)(hb % HH) * EE * EE;
        Chg = qp.oh[proj] + (long)hb * TT * EE;
        Clg = qp.ol[proj] + (long)hb * TT * EE;
        bias = qp.bias[proj] + (hb % HH) * EE;
        itEnd = K >> 5;
    } else if (CMODE == 3) {
        const int hb = z >> 2, slice = z & 3;
        Ahg += (long)hb * TT * TT; Alg += (long)hb * TT * TT;
        Bhg += (long)hb * TT * EE; Blg += (long)hb * TT * EE;
        Cf  += (long)z * TT * EE;
        const int kB = slice * 512;
        const int kE = min(m0 + 128, kB + 512);
        if (kB >= kE) return;
        it0 = kB >> 5;
        itEnd = kE >> 5;
    } else {
        const long za = zoff(oa, z), zb = zoff(ob, z), zc = zoff(oc, z);
        Ahg += za; Alg += za;
        Bhg += zb; Blg += zb;
        if (EPI == 0) Cf += zc; else { Chg += zc; Clg += zc; }
        if (EPI == 1 || EPI == 2) bias += zoff(obias, z);
        if (CMODE == 1 && m0 < n0) return;
        itEnd = K >> 5;
    }

    extern __shared__ bf16 dyn[];
    __shared__ float scol[8][128];

    const int tid  = threadIdx.x;
    const int lane = tid & 31;
    const int wid  = tid >> 5;
    const int wm   = wid & 3;
    const int wn   = wid >> 2;

    float acc[2][8][4];
#pragma unroll
    for (int i = 0; i < 2; i++)
#pragma unroll
        for (int j = 0; j < 8; j++)
#pragma unroll
            for (int r = 0; r < 4; r++) acc[i][j][r] = 0.f;

    const int lr = tid >> 1;
    const int lc = (tid & 1) * 16;
    const bf16* Agh = Ahg + (size_t)(m0 + lr) * lda + lc;
    const bf16* Agl = Alg + (size_t)(m0 + lr) * lda + lc;
    const bf16* Bgh = Bhg + (size_t)(n0 + lr) * ldb + lc;
    const bf16* Bgl = Blg + (size_t)(n0 + lr) * ldb + lc;
    const int ldst = lr * ROWS_LD + lc;

    const int m8 = lane >> 3, r8 = lane & 7;
    const int aoff = (wm * 32 + (m8 & 1) * 8 + r8) * ROWS_LD + (m8 >> 1) * 8;
    const int boff = (wn * 64 + (m8 >> 1) * 8 + r8) * ROWS_LD + (m8 & 1) * 8;

#define ISSUE(it, buf)                                                        \
    do {                                                                      \
        bf16* st = dyn + (buf) * STAGE_ELEMS;                                 \
        const int ko = (it) << 5;                                             \
        cpa16(st + ldst,         Agh + ko); cpa16(st + ldst + 8,         Agh + ko + 8); \
        cpa16(st + 5120 + ldst,  Agl + ko); cpa16(st + 5120 + ldst + 8,  Agl + ko + 8); \
        cpa16(st + 10240 + ldst, Bgh + ko); cpa16(st + 10240 + ldst + 8, Bgh + ko + 8); \
        cpa16(st + 15360 + ldst, Bgl + ko); cpa16(st + 15360 + ldst + 8, Bgl + ko + 8); \
        asm volatile("cp.async.commit_group;");                               \
    } while (0)

    ISSUE(it0, 0);

    for (int it = it0, r = 0; it < itEnd; ++it, ++r) {
        if (it + 1 < itEnd) {
            ISSUE(it + 1, (r + 1) & 1);
            asm volatile("cp.async.wait_group 1;" ::: "memory");
        } else {
            asm volatile("cp.async.wait_group 0;" ::: "memory");
        }
        __syncthreads();

        const bf16* st = dyn + (r & 1) * STAGE_ELEMS;
        const bf16* sAh = st;
        const bf16* sAl = st + 5120;
        const bf16* sBh = st + 10240;
        const bf16* sBl = st + 15360;

#pragma unroll
        for (int s = 0; s < 2; s++) {
            const int kk = s * 16;
            uint32_t ah[2][4], al[2][4];
            ldsm4(ah[0], sAh + aoff + kk);
            ldsm4(ah[1], sAh + aoff + 640 + kk);
            ldsm4(al[0], sAl + aoff + kk);
            ldsm4(al[1], sAl + aoff + 640 + kk);
#pragma unroll
            for (int ntp = 0; ntp < 4; ntp++) {
                uint32_t bh[4], bl[4];
                ldsm4(bh, sBh + boff + ntp * 640 + kk);
                ldsm4(bl, sBl + boff + ntp * 640 + kk);
                // combo 1: Ah x Bh over all 4 accumulators of this B tile
#pragma unroll
                for (int j = 0; j < 2; j++)
#pragma unroll
                    for (int mt = 0; mt < 2; mt++)
                        mma_bf16(acc[mt][2 * ntp + j], ah[mt], bh[2 * j], bh[2 * j + 1]);
                // combo 2: Ah x Bl
#pragma unroll
                for (int j = 0; j < 2; j++)
#pragma unroll
                    for (int mt = 0; mt < 2; mt++)
                        mma_bf16(acc[mt][2 * ntp + j], ah[mt], bl[2 * j], bl[2 * j + 1]);
                // combo 3: Al x Bh
#pragma unroll
                for (int j = 0; j < 2; j++)
#pragma unroll
                    for (int mt = 0; mt < 2; mt++)
                        mma_bf16(acc[mt][2 * ntp + j], al[mt], bh[2 * j], bh[2 * j + 1]);
            }
        }
        __syncthreads();
    }
#undef ISSUE

    // ---------------- epilogue ----------------
#pragma unroll
    for (int mt = 0; mt < 2; mt++) {
#pragma unroll
        for (int nt = 0; nt < 8; nt++) {
            const int r0 = m0 + wm * 32 + mt * 16 + (lane >> 2);
            const int cb = n0 + wn * 64 + nt * 8 + (lane & 3) * 2;
            float v[4];
#pragma unroll
            for (int r = 0; r < 4; r++) v[r] = acc[mt][nt][r] * scale;
            if (EPI == 1 || EPI == 2) {
                float b0 = bias[cb], b1 = bias[cb + 1];
                v[0] += b0; v[1] += b1; v[2] += b0; v[3] += b1;
            }
            if (EPI == 2) {
#pragma unroll
                for (int r = 0; r < 4; r++)
                    v[r] = 0.5f * v[r] * (1.0f + erff(v[r] * 0.70710678118654752f));
            }
            if (EPI == 3) {
                v[0] = (r0 < cb)         ? 0.f : __expf(v[0]);
                v[1] = (r0 < cb + 1)     ? 0.f : __expf(v[1]);
                v[2] = (r0 + 8 < cb)     ? 0.f : __expf(v[2]);
                v[3] = (r0 + 8 < cb + 1) ? 0.f : __expf(v[3]);
                float s0 = v[0] + v[2], s1 = v[1] + v[3];
#pragma unroll
                for (int o = 4; o < 32; o <<= 1) {
                    s0 += __shfl_xor_sync(0xFFFFFFFFu, s0, o);
                    s1 += __shfl_xor_sync(0xFFFFFFFFu, s1, o);
                }
                if (lane < 4) {
                    scol[wm * 2 + mt][wn * 64 + nt * 8 + lane * 2]     = s0;
                    scol[wm * 2 + mt][wn * 64 + nt * 8 + lane * 2 + 1] = s1;
                }
            }
            if (EPI == 0) {
                *(float2*)&Cf[(size_t)r0 * ldc + cb]       = make_float2(v[0], v[1]);
                *(float2*)&Cf[(size_t)(r0 + 8) * ldc + cb] = make_float2(v[2], v[3]);
            } else {
                bf16 h0, l0, h1, l1;
                split_bf16(v[0], h0, l0); split_bf16(v[1], h1, l1);
                *(uint32_t*)&Chg[(size_t)r0 * ldc + cb] = pack2(h0, h1);
                *(uint32_t*)&Clg[(size_t)r0 * ldc + cb] = pack2(l0, l1);
                split_bf16(v[2], h0, l0); split_bf16(v[3], h1, l1);
                *(uint32_t*)&Chg[(size_t)(r0 + 8) * ldc + cb] = pack2(h0, h1);
                *(uint32_t*)&Clg[(size_t)(r0 + 8) * ldc + cb] = pack2(l0, l1);
            }
        }
    }

    if (EPI == 3) {
        __syncthreads();
        if (tid < 128) {
            float p = 0.f;
#pragma unroll
            for (int sl = 0; sl < 8; sl++) p += scol[sl][tid];
            psum[((size_t)z * (TT / 128) + blockIdx.y) * TT + n0 + tid] = p;
        }
    }
}

// ---------------------------------------------------------------------------
__global__ void colsum_inv(const float* __restrict__ psum, float* __restrict__ inv)
{
    const int s = blockIdx.x * blockDim.x + threadIdx.x;
    const int z = blockIdx.y;
    float sum = 0.f;
    for (int mb = s >> 7; mb < TT / 128; mb++)
        sum += psum[((size_t)z * (TT / 128) + mb) * TT + s];
    inv[(size_t)z * TT + s] = 1.f / sum;
}

__global__ void attn_reduce(const float* __restrict__ part, float* __restrict__ cc)
{
    const size_t i = (size_t)blockIdx.x * blockDim.x + threadIdx.x;
    const int e  = (int)(i & (EE - 1));
    const int t  = (int)((i >> 7) & (TT - 1));
    const int hb = (int)(i >> 18);
    const int b = hb >> 3, h = hb & 7;
    const int nsl = (((t >> 7) + 1) * 128 + 511) >> 9;
    const float* p = part + ((size_t)hb * 4) * TT * EE + (size_t)t * EE + e;
    float s = 0.f;
    for (int sl = 0; sl < nsl; sl++) s += p[(size_t)sl * TT * EE];
    cc[(size_t)b * TT * DD + (size_t)t * DD + h * EE + e] = s;
}

__global__ void split_tr(const float* __restrict__ src, bf16* __restrict__ oh,
                         bf16* __restrict__ ol, int R, int C)
{
    __shared__ float t[32][33];
    const size_t zo = (size_t)blockIdx.z * R * C;
    const int c0 = blockIdx.x * 32, r0 = blockIdx.y * 32;
    const int tx = threadIdx.x, ty = threadIdx.y;
    for (int i = ty; i < 32; i += 8)
        t[i][tx] = src[zo + (size_t)(r0 + i) * C + c0 + tx];
    __syncthreads();
    for (int i = ty; i < 32; i += 8) {
        float v = t[tx][i];
        bf16 h, l; split_bf16(v, h, l);
        oh[zo + (size_t)(c0 + i) * R + r0 + tx] = h;
        ol[zo + (size_t)(c0 + i) * R + r0 + tx] = l;
    }
}

__global__ void tr_planes_scaled(const bf16* __restrict__ ih, const bf16* __restrict__ il,
                                 const float* __restrict__ inv,
                                 bf16* __restrict__ oh, bf16* __restrict__ ol,
                                 int R, int C)
{
    __shared__ bf16 th[32][33], tl[32][33];
    const size_t zo = (size_t)blockIdx.z * R * C;
    const int c0 = blockIdx.x * 32, r0 = blockIdx.y * 32;
    const int tx = threadIdx.x, ty = threadIdx.y;
    for (int i = ty; i < 32; i += 8) {
        th[i][tx] = ih[zo + (size_t)(r0 + i) * C + c0 + tx];
        tl[i][tx] = il[zo + (size_t)(r0 + i) * C + c0 + tx];
    }
    __syncthreads();
    const float invv = inv[(size_t)blockIdx.z * R + r0 + tx];
    for (int i = ty; i < 32; i += 8) {
        float v = (__bfloat162float(th[tx][i]) + __bfloat162float(tl[tx][i])) * invv;
        bf16 h, l; split_bf16(v, h, l);
        oh[zo + (size_t)(c0 + i) * R + r0 + tx] = h;
        ol[zo + (size_t)(c0 + i) * R + r0 + tx] = l;
    }
}

__global__ void ln_split(const float* __restrict__ x, const float* __restrict__ g,
                         const float* __restrict__ b, bf16* __restrict__ yh,
                         bf16* __restrict__ yl, int D)
{
    const long row = blockIdx.x;
    const float* xr = x + row * D;

    float s = 0.f, s2 = 0.f;
    for (int i = threadIdx.x; i < D; i += blockDim.x) {
        float v = xr[i];
        s += v; s2 += v * v;
    }
#pragma unroll
    for (int o = 16; o; o >>= 1) {
        s  += __shfl_xor_sync(0xFFFFFFFFu, s,  o);
        s2 += __shfl_xor_sync(0xFFFFFFFFu, s2, o);
    }
    __shared__ float shs[8], shs2[8];
    __shared__ float mu_s, ri_s;
    const int w = threadIdx.x >> 5, l = threadIdx.x & 31;
    if (l == 0) { shs[w] = s; shs2[w] = s2; }
    __syncthreads();
    if (threadIdx.x == 0) {
        const int nw = blockDim.x >> 5;
        float ts = 0.f, ts2 = 0.f;
        for (int i = 0; i < nw; i++) { ts += shs[i]; ts2 += shs2[i]; }
        float mu  = ts / D;
        float var = ts2 / D - mu * mu;
        mu_s = mu;
        ri_s = rsqrtf(var + 1e-5f);
    }
    __syncthreads();
    const float mu = mu_s, ri = ri_s;
    for (int i = threadIdx.x; i < D; i += blockDim.x) {
        float v = (xr[i] - mu) * ri * g[i] + b[i];
        bf16 h, lo; split_bf16(v, h, lo);
        yh[row * D + i] = h;
        yl[row * D + i] = lo;
    }
}

__global__ void mlp2_reduce(const float* __restrict__ part, const float* __restrict__ b2,
                            float* __restrict__ out)
{
    const size_t P = (size_t)BB * TT * EE;
    const size_t i = (size_t)blockIdx.x * blockDim.x + threadIdx.x;
    const int n = (int)(i & (EE - 1));
    out[i] = part[i] + part[i + P] + part[i + 2 * P] + part[i + 3 * P] + b2[n];
}

// ---------------------------------------------------------------------------
extern "C" void kernel_launch(void* const* d_in, const int* in_sizes, int n_in,
                              void* d_out, int out_size)
{
    const float* X    = (const float*)d_in[0];
    const float* ln1g = (const float*)d_in[1];
    const float* ln1b = (const float*)d_in[2];
    const float* Wq   = (const float*)d_in[3];
    const float* bq   = (const float*)d_in[4];
    const float* Wk   = (const float*)d_in[5];
    const float* bk   = (const float*)d_in[6];
    const float* Wv   = (const float*)d_in[7];
    const float* bv   = (const float*)d_in[8];
    const float* ln2g = (const float*)d_in[9];
    const float* ln2b = (const float*)d_in[10];
    const float* W1   = (const float*)d_in[11];
    const float* b1   = (const float*)d_in[12];
    const float* W2   = (const float*)d_in[13];
    const float* b2   = (const float*)d_in[14];
    float* out = (float*)d_out;

    float *cc, *part, *partA, *psum, *inv;
    bf16 *Sh, *Sl, *Xnh, *Xnl, *qh, *ql, *kh, *kl, *vh, *vl, *vth, *vtl;
    bf16 *cch, *ccl, *midh, *midl;
    bf16 *Wqh, *Wql, *Wkh, *Wkl, *Wvh, *Wvl, *W1h, *W1l, *W2h, *W2l;
    cudaGetSymbolAddress((void**)&Sh,   g_Sh);
    cudaGetSymbolAddress((void**)&Sl,   g_Sl);
    cudaGetSymbolAddress((void**)&psum, g_psum);
    cudaGetSymbolAddress((void**)&inv,  g_inv);
    cudaGetSymbolAddress((void**)&Xnh,  g_Xnh);
    cudaGetSymbolAddress((void**)&Xnl,  g_Xnl);
    cudaGetSymbolAddress((void**)&qh,   g_qh);
    cudaGetSymbolAddress((void**)&ql,   g_ql);
    cudaGetSymbolAddress((void**)&kh,   g_kh);
    cudaGetSymbolAddress((void**)&kl,   g_kl);
    cudaGetSymbolAddress((void**)&vh,   g_vh);
    cudaGetSymbolAddress((void**)&vl,   g_vl);
    cudaGetSymbolAddress((void**)&vth,  g_vth);
    cudaGetSymbolAddress((void**)&vtl,  g_vtl);
    cudaGetSymbolAddress((void**)&cc,   g_cc);
    cudaGetSymbolAddress((void**)&cch,  g_cch);
    cudaGetSymbolAddress((void**)&ccl,  g_ccl);
    cudaGetSymbolAddress((void**)&midh, g_midh);
    cudaGetSymbolAddress((void**)&midl, g_midl);
    cudaGetSymbolAddress((void**)&Wqh,  g_Wqh);
    cudaGetSymbolAddress((void**)&Wql,  g_Wql);
    cudaGetSymbolAddress((void**)&Wkh,  g_Wkh);
    cudaGetSymbolAddress((void**)&Wkl,  g_Wkl);
    cudaGetSymbolAddress((void**)&Wvh,  g_Wvh);
    cudaGetSymbolAddress((void**)&Wvl,  g_Wvl);
    cudaGetSymbolAddress((void**)&W1h,  g_W1h);
    cudaGetSymbolAddress((void**)&W1l,  g_W1l);
    cudaGetSymbolAddress((void**)&W2h,  g_W2h);
    cudaGetSymbolAddress((void**)&W2l,  g_W2l);
    cudaGetSymbolAddress((void**)&part, g_part);
    cudaGetSymbolAddress((void**)&partA, g_partA);

    const ZOff z0   = {1, 1, 0, 0};
    const ZOff oQKV = {1, 1, (long)TT * EE, 0};
    const ZOff oS   = {1, 1, (long)TT * TT, 0};
    const ZOff oK1  = {1, 4, 0, 1024};
    const ZOff oP   = {1, 4, 0, (long)BB * TT * EE};

    QKVP qp{};
    qp.wh[0] = Wqh; qp.wh[1] = Wkh; qp.wh[2] = Wvh;
    qp.wl[0] = Wql; qp.wl[1] = Wkl; qp.wl[2] = Wvl;
    qp.bias[0] = bq; qp.bias[1] = bk; qp.bias[2] = bv;
    qp.oh[0] = qh; qp.oh[1] = kh; qp.oh[2] = vh;
    qp.ol[0] = ql; qp.ol[1] = kl; qp.ol[2] = vl;
    QKVP qdummy{};

    const int SMEM = 2 * STAGE_ELEMS * (int)sizeof(bf16);   // 80 KB
    cudaFuncSetAttribute(gemm_bt<0, 0>, cudaFuncAttributeMaxDynamicSharedMemorySize, SMEM);
    cudaFuncSetAttribute(gemm_bt<0, 3>, cudaFuncAttributeMaxDynamicSharedMemorySize, SMEM);
    cudaFuncSetAttribute(gemm_bt<1, 4>, cudaFuncAttributeMaxDynamicSharedMemorySize, SMEM);
    cudaFuncSetAttribute(gemm_bt<2, 0>, cudaFuncAttributeMaxDynamicSharedMemorySize, SMEM);
    cudaFuncSetAttribute(gemm_bt<3, 1>, cudaFuncAttributeMaxDynamicSharedMemorySize, SMEM);

    dim3 tb(32, 8);

    // 0. one-time weight split+transpose
    split_tr<<<dim3(4, 4, HH), tb>>>(Wq, Wqh, Wql, EE, EE);
    split_tr<<<dim3(4, 4, HH), tb>>>(Wk, Wkh, Wkl, EE, EE);
    split_tr<<<dim3(4, 4, HH), tb>>>(Wv, Wvh, Wvl, EE, EE);
    split_tr<<<dim3(FF / 32, DD / 32, 1), tb>>>(W1, W1h, W1l, DD, FF);
    split_tr<<<dim3(EE / 32, FF / 32, 1), tb>>>(W2, W2h, W2l, FF, EE);

    // 1. LN1 -> Xn planes
    ln_split<<<BB * TT, 128>>>(X, ln1g, ln1b, Xnh, Xnl, EE);

    // 2. fused QKV projections
    dim3 gqkv(1, TT / 128, 3 * BB * HH);
    gemm_bt<1, 4><<<gqkv, 256, SMEM>>>(Xnh, Xnl, nullptr, nullptr, nullptr, nullptr, nullptr,
                                       nullptr, nullptr,
                                       TT, EE, EE, EE, EE, EE, 1.f, z0, z0, z0, z0, qp);

    // 3. e = exp(Q@K^T/sqrt(E)) with causal zeroing -> planes + psums
    dim3 gsc(TT / 128, TT / 128, BB * HH);
    gemm_bt<3, 1><<<gsc, 256, SMEM>>>(qh, ql, kh, kl, nullptr, Sh, Sl, nullptr, psum,
                                      TT, TT, EE, EE, EE, TT,
                                      0.08838834764831845f, oQKV, oQKV, oS, z0, qdummy);

    // 4. column sums -> inv ;  V transpose scaled by inv
    colsum_inv<<<dim3(TT / 256, BB * HH), 256>>>(psum, inv);
    tr_planes_scaled<<<dim3(EE / 32, TT / 32, BB * HH), tb>>>(vh, vl, inv, vth, vtl, TT, EE);

    // 5. attnV split-K -> partials -> cc
    dim3 gav(1, TT / 128, BB * HH * 4);
    gemm_bt<0, 3><<<gav, 256, SMEM>>>(Sh, Sl, vth, vtl, partA, nullptr, nullptr, nullptr, nullptr,
                                      TT, EE, TT, TT, TT, EE, 1.f, z0, z0, z0, z0, qdummy);
    attn_reduce<<<(BB * HH * TT * EE) / 256, 256>>>(partA, cc);

    // 6. LN2 -> cc planes
    ln_split<<<BB * TT, 256>>>(cc, ln2g, ln2b, cch, ccl, DD);

    // 7. mid = gelu(cc @ W1 + b1)
    dim3 g1(FF / 128, (BB * TT) / 128, 1);
    gemm_bt<2, 0><<<g1, 256, SMEM>>>(cch, ccl, W1h, W1l, nullptr, midh, midl, b1, nullptr,
                                     BB * TT, FF, DD, DD, DD, FF, 1.f, z0, z0, z0, z0, qdummy);

    // 8. out = mid @ W2 + b2 : split-K x4, then reduce
    dim3 g2(1, (BB * TT) / 128, 4);
    gemm_bt<0, 0><<<g2, 256, SMEM>>>(midh, midl, W2h, W2l, part, nullptr, nullptr, nullptr, nullptr,
                                     BB * TT, EE, 1024, FF, FF, EE, 1.f, oK1, oK1, oP, z0, qdummy);
    mlp2_reduce<<<(BB * TT * EE) / 256, 256>>>(part, b2, out);
}

// round 17
// speedup vs baseline: 4.8953x; 1.2856x over previous
#include <cuda_runtime.h>
#include <cuda_fp16.h>
#include <math.h>
#include <stdint.h>

#define BB 4
#define TT 2048
#define EE 128
#define HH 8
#define DD 1024
#define FF 4096

typedef __half fp16;

// ---------------------------------------------------------------------------
// Scratch (static device globals; no allocation anywhere)
// ---------------------------------------------------------------------------
__device__ fp16  g_S  [(size_t)BB*HH*TT*TT];          // attn e (fp16)
__device__ float g_psum[(size_t)BB*HH*(TT/128)*TT];
__device__ float g_inv [(size_t)BB*HH*TT];
__device__ fp16  g_Xn [(size_t)BB*TT*EE];
__device__ fp16  g_q  [(size_t)BB*HH*TT*EE];
__device__ fp16  g_k  [(size_t)BB*HH*TT*EE];
__device__ fp16  g_v  [(size_t)BB*HH*TT*EE];
__device__ fp16  g_vt [(size_t)BB*HH*TT*EE];
__device__ float g_cc [(size_t)BB*TT*DD];
__device__ fp16  g_ccp[(size_t)BB*TT*DD];
__device__ fp16  g_mid[(size_t)BB*TT*FF];
__device__ fp16  g_Wq [(size_t)HH*EE*EE];
__device__ fp16  g_Wk [(size_t)HH*EE*EE];
__device__ fp16  g_Wv [(size_t)HH*EE*EE];
__device__ fp16  g_W1 [(size_t)DD*FF];                // [F][D]
__device__ fp16  g_W2 [(size_t)FF*EE];                // [E][F]
__device__ float g_part[(size_t)4*BB*TT*EE];
__device__ float g_partA[(size_t)4*BB*HH*TT*EE];

// ---------------------------------------------------------------------------
struct ZOff { int dv; int md; long sd; long sm; };
__device__ __forceinline__ long zoff(ZOff o, int z) {
    return (long)(z / o.dv) * o.sd + (long)(z % o.md) * o.sm;
}
struct QKVP {
    const fp16* w[3];
    const float* bias[3];
    fp16* o[3];
};

__device__ __forceinline__ uint32_t pack2h(float a, float b) {
    __half2 h = __floats2half2_rn(a, b);
    return *(uint32_t*)&h;
}
__device__ __forceinline__ void mma_f16(float* c,
                                        const uint32_t* a, uint32_t b0, uint32_t b1) {
    asm volatile(
        "mma.sync.aligned.m16n8k16.row.col.f32.f16.f16.f32 "
        "{%0,%1,%2,%3}, {%4,%5,%6,%7}, {%8,%9}, {%0,%1,%2,%3};"
        : "+f"(c[0]), "+f"(c[1]), "+f"(c[2]), "+f"(c[3])
        : "r"(a[0]), "r"(a[1]), "r"(a[2]), "r"(a[3]), "r"(b0), "r"(b1));
}
__device__ __forceinline__ void ldsm4(uint32_t* r, const fp16* p) {
    uint32_t a = (uint32_t)__cvta_generic_to_shared(p);
    asm volatile("ldmatrix.sync.aligned.m8n8.x4.shared.b16 {%0,%1,%2,%3}, [%4];"
        : "=r"(r[0]), "=r"(r[1]), "=r"(r[2]), "=r"(r[3]) : "r"(a));
}
__device__ __forceinline__ void cpa16(fp16* smem, const fp16* gmem) {
    uint32_t s = (uint32_t)__cvta_generic_to_shared(smem);
    asm volatile("cp.async.cg.shared.global [%0], [%1], 16;" :: "r"(s), "l"(gmem));
}

// SMEM stage: A[128x40] then B[128x40] halfs -> 10240 halfs = 20 KB/stage,
// 2 stages = 40 KB dynamic SMEM.
#define STAGE_ELEMS 10240
#define ROWS_LD 40

// ---------------------------------------------------------------------------
// fp16 tensor-core GEMM. C = act(scale * A @ B^T + bias)
//   EPI   : 0 f32*scale -> Cf ; 1 +bias -> fp16 ; 2 +bias+gelu -> fp16
//           3 exp(scale*acc), causal zero -> fp16 + column psums
//   CMODE : 0 normal; 1 skip blocks above diagonal;
//           3 attnV split-K (z = hb*4+slice); 4 fused QKV (z = proj*BH+hb)
// ---------------------------------------------------------------------------
template <int EPI, int CMODE>
__global__ __launch_bounds__(256, 2) void gemm_h(
    const fp16* __restrict__ Ag, const fp16* __restrict__ Bg,
    float* __restrict__ Cf, fp16* __restrict__ Ch,
    const float* __restrict__ bias, float* __restrict__ psum,
    int M, int N, int K, int lda, int ldb, int ldc, float scale,
    ZOff oa, ZOff ob, ZOff oc, ZOff obias, QKVP qp)
{
    const int z = blockIdx.z;
    const int n0 = blockIdx.x * 128;
    const int m0 = blockIdx.y * 128;

    int it0 = 0, itEnd;

    if (CMODE == 4) {
        const int proj = z / (BB * HH);
        const int hb   = z % (BB * HH);
        Ag += (long)(hb / HH) * TT * EE;
        Bg = qp.w[proj] + (long)(hb % HH) * EE * EE;
        Ch = qp.o[proj] + (long)hb * TT * EE;
        bias = qp.bias[proj] + (hb % HH) * EE;
        itEnd = K >> 5;
    } else if (CMODE == 3) {
        const int hb = z >> 2, slice = z & 3;
        Ag += (long)hb * TT * TT;
        Bg += (long)hb * TT * EE;
        Cf += (long)z * TT * EE;
        const int kB = slice * 512;
        const int kE = min(m0 + 128, kB + 512);
        if (kB >= kE) return;
        it0 = kB >> 5;
        itEnd = kE >> 5;
    } else {
        Ag += zoff(oa, z);
        Bg += zoff(ob, z);
        const long zc = zoff(oc, z);
        if (EPI == 0) Cf += zc; else Ch += zc;
        if (EPI == 1 || EPI == 2) bias += zoff(obias, z);
        if (CMODE == 1 && m0 < n0) return;
        itEnd = K >> 5;
    }

    extern __shared__ fp16 dyn[];
    __shared__ float scol[8][128];

    const int tid  = threadIdx.x;
    const int lane = tid & 31;
    const int wid  = tid >> 5;
    const int wm   = wid & 3;
    const int wn   = wid >> 2;

    float acc[2][8][4];
#pragma unroll
    for (int i = 0; i < 2; i++)
#pragma unroll
        for (int j = 0; j < 8; j++)
#pragma unroll
            for (int r = 0; r < 4; r++) acc[i][j][r] = 0.f;

    const int lr = tid >> 1;
    const int lc = (tid & 1) * 16;
    const fp16* Agp = Ag + (size_t)(m0 + lr) * lda + lc;
    const fp16* Bgp = Bg + (size_t)(n0 + lr) * ldb + lc;
    const int ldst = lr * ROWS_LD + lc;

    const int m8 = lane >> 3, r8 = lane & 7;
    const int aoff = (wm * 32 + (m8 & 1) * 8 + r8) * ROWS_LD + (m8 >> 1) * 8;
    const int boff = (wn * 64 + (m8 >> 1) * 8 + r8) * ROWS_LD + (m8 & 1) * 8;

#define ISSUE(it, buf)                                                        \
    do {                                                                      \
        fp16* st = dyn + (buf) * STAGE_ELEMS;                                 \
        const int ko = (it) << 5;                                             \
        cpa16(st + ldst,        Agp + ko); cpa16(st + ldst + 8,        Agp + ko + 8); \
        cpa16(st + 5120 + ldst, Bgp + ko); cpa16(st + 5120 + ldst + 8, Bgp + ko + 8); \
        asm volatile("cp.async.commit_group;");                               \
    } while (0)

    ISSUE(it0, 0);

    for (int it = it0, r = 0; it < itEnd; ++it, ++r) {
        if (it + 1 < itEnd) {
            ISSUE(it + 1, (r + 1) & 1);
            asm volatile("cp.async.wait_group 1;" ::: "memory");
        } else {
            asm volatile("cp.async.wait_group 0;" ::: "memory");
        }
        __syncthreads();

        const fp16* st = dyn + (r & 1) * STAGE_ELEMS;
        const fp16* sA = st;
        const fp16* sB = st + 5120;

#pragma unroll
        for (int s = 0; s < 2; s++) {
            const int kk = s * 16;
            uint32_t a[2][4];
            ldsm4(a[0], sA + aoff + kk);
            ldsm4(a[1], sA + aoff + 640 + kk);
#pragma unroll
            for (int ntp = 0; ntp < 4; ntp++) {
                uint32_t b[4];
                ldsm4(b, sB + boff + ntp * 640 + kk);
#pragma unroll
                for (int j = 0; j < 2; j++)
#pragma unroll
                    for (int mt = 0; mt < 2; mt++)
                        mma_f16(acc[mt][2 * ntp + j], a[mt], b[2 * j], b[2 * j + 1]);
            }
        }
        __syncthreads();
    }
#undef ISSUE

    // ---------------- epilogue ----------------
#pragma unroll
    for (int mt = 0; mt < 2; mt++) {
#pragma unroll
        for (int nt = 0; nt < 8; nt++) {
            const int r0 = m0 + wm * 32 + mt * 16 + (lane >> 2);
            const int cb = n0 + wn * 64 + nt * 8 + (lane & 3) * 2;
            float v[4];
#pragma unroll
            for (int r = 0; r < 4; r++) v[r] = acc[mt][nt][r] * scale;
            if (EPI == 1 || EPI == 2) {
                float b0 = bias[cb], b1 = bias[cb + 1];
                v[0] += b0; v[1] += b1; v[2] += b0; v[3] += b1;
            }
            if (EPI == 2) {
#pragma unroll
                for (int r = 0; r < 4; r++)
                    v[r] = 0.5f * v[r] * (1.0f + erff(v[r] * 0.70710678118654752f));
            }
            if (EPI == 3) {
                v[0] = (r0 < cb)         ? 0.f : __expf(v[0]);
                v[1] = (r0 < cb + 1)     ? 0.f : __expf(v[1]);
                v[2] = (r0 + 8 < cb)     ? 0.f : __expf(v[2]);
                v[3] = (r0 + 8 < cb + 1) ? 0.f : __expf(v[3]);
                float s0 = v[0] + v[2], s1 = v[1] + v[3];
#pragma unroll
                for (int o = 4; o < 32; o <<= 1) {
                    s0 += __shfl_xor_sync(0xFFFFFFFFu, s0, o);
                    s1 += __shfl_xor_sync(0xFFFFFFFFu, s1, o);
                }
                if (lane < 4) {
                    scol[wm * 2 + mt][wn * 64 + nt * 8 + lane * 2]     = s0;
                    scol[wm * 2 + mt][wn * 64 + nt * 8 + lane * 2 + 1] = s1;
                }
            }
            if (EPI == 0) {
                *(float2*)&Cf[(size_t)r0 * ldc + cb]       = make_float2(v[0], v[1]);
                *(float2*)&Cf[(size_t)(r0 + 8) * ldc + cb] = make_float2(v[2], v[3]);
            } else {
                *(uint32_t*)&Ch[(size_t)r0 * ldc + cb]       = pack2h(v[0], v[1]);
                *(uint32_t*)&Ch[(size_t)(r0 + 8) * ldc + cb] = pack2h(v[2], v[3]);
            }
        }
    }

    if (EPI == 3) {
        __syncthreads();
        if (tid < 128) {
            float p = 0.f;
#pragma unroll
            for (int sl = 0; sl < 8; sl++) p += scol[sl][tid];
            psum[((size_t)z * (TT / 128) + blockIdx.y) * TT + n0 + tid] = p;
        }
    }
}

// ---------------------------------------------------------------------------
__global__ void colsum_inv(const float* __restrict__ psum, float* __restrict__ inv)
{
    const int s = blockIdx.x * blockDim.x + threadIdx.x;
    const int z = blockIdx.y;
    float sum = 0.f;
    for (int mb = s >> 7; mb < TT / 128; mb++)
        sum += psum[((size_t)z * (TT / 128) + mb) * TT + s];
    inv[(size_t)z * TT + s] = 1.f / sum;
}

__global__ void attn_reduce(const float* __restrict__ part, float* __restrict__ cc)
{
    const size_t i = (size_t)blockIdx.x * blockDim.x + threadIdx.x;
    const int e  = (int)(i & (EE - 1));
    const int t  = (int)((i >> 7) & (TT - 1));
    const int hb = (int)(i >> 18);
    const int b = hb >> 3, h = hb & 7;
    const int nsl = (((t >> 7) + 1) * 128 + 511) >> 9;
    const float* p = part + ((size_t)hb * 4) * TT * EE + (size_t)t * EE + e;
    float s = 0.f;
    for (int sl = 0; sl < nsl; sl++) s += p[(size_t)sl * TT * EE];
    cc[(size_t)b * TT * DD + (size_t)t * DD + h * EE + e] = s;
}

// Split+transpose f32 [R][C] -> fp16 [C][R]; z = matrix index.
__global__ void split_tr(const float* __restrict__ src, fp16* __restrict__ o, int R, int C)
{
    __shared__ float t[32][33];
    const size_t zo = (size_t)blockIdx.z * R * C;
    const int c0 = blockIdx.x * 32, r0 = blockIdx.y * 32;
    const int tx = threadIdx.x, ty = threadIdx.y;
    for (int i = ty; i < 32; i += 8)
        t[i][tx] = src[zo + (size_t)(r0 + i) * C + c0 + tx];
    __syncthreads();
    for (int i = ty; i < 32; i += 8)
        o[zo + (size_t)(c0 + i) * R + r0 + tx] = __float2half(t[tx][i]);
}

// Transpose V [T][E] -> [E][T], scaling row t by inv[t].
__global__ void tr_scaled(const fp16* __restrict__ in, const float* __restrict__ inv,
                          fp16* __restrict__ o, int R, int C)
{
    __shared__ fp16 t[32][33];
    const size_t zo = (size_t)blockIdx.z * R * C;
    const int c0 = blockIdx.x * 32, r0 = blockIdx.y * 32;
    const int tx = threadIdx.x, ty = threadIdx.y;
    for (int i = ty; i < 32; i += 8)
        t[i][tx] = in[zo + (size_t)(r0 + i) * C + c0 + tx];
    __syncthreads();
    const float invv = inv[(size_t)blockIdx.z * R + r0 + tx];
    for (int i = ty; i < 32; i += 8)
        o[zo + (size_t)(c0 + i) * R + r0 + tx] = __float2half(__half2float(t[tx][i]) * invv);
}

__global__ void ln_h(const float* __restrict__ x, const float* __restrict__ g,
                     const float* __restrict__ b, fp16* __restrict__ y, int D)
{
    const long row = blockIdx.x;
    const float* xr = x + row * D;

    float s = 0.f, s2 = 0.f;
    for (int i = threadIdx.x; i < D; i += blockDim.x) {
        float v = xr[i];
        s += v; s2 += v * v;
    }
#pragma unroll
    for (int o = 16; o; o >>= 1) {
        s  += __shfl_xor_sync(0xFFFFFFFFu, s,  o);
        s2 += __shfl_xor_sync(0xFFFFFFFFu, s2, o);
    }
    __shared__ float shs[8], shs2[8];
    __shared__ float mu_s, ri_s;
    const int w = threadIdx.x >> 5, l = threadIdx.x & 31;
    if (l == 0) { shs[w] = s; shs2[w] = s2; }
    __syncthreads();
    if (threadIdx.x == 0) {
        const int nw = blockDim.x >> 5;
        float ts = 0.f, ts2 = 0.f;
        for (int i = 0; i < nw; i++) { ts += shs[i]; ts2 += shs2[i]; }
        float mu  = ts / D;
        float var = ts2 / D - mu * mu;
        mu_s = mu;
        ri_s = rsqrtf(var + 1e-5f);
    }
    __syncthreads();
    const float mu = mu_s, ri = ri_s;
    for (int i = threadIdx.x; i < D; i += blockDim.x)
        y[row * D + i] = __float2half((xr[i] - mu) * ri * g[i] + b[i]);
}

__global__ void mlp2_reduce(const float* __restrict__ part, const float* __restrict__ b2,
                            float* __restrict__ out)
{
    const size_t P = (size_t)BB * TT * EE;
    const size_t i = (size_t)blockIdx.x * blockDim.x + threadIdx.x;
    const int n = (int)(i & (EE - 1));
    out[i] = part[i] + part[i + P] + part[i + 2 * P] + part[i + 3 * P] + b2[n];
}

// ---------------------------------------------------------------------------
extern "C" void kernel_launch(void* const* d_in, const int* in_sizes, int n_in,
                              void* d_out, int out_size)
{
    const float* X    = (const float*)d_in[0];
    const float* ln1g = (const float*)d_in[1];
    const float* ln1b = (const float*)d_in[2];
    const float* Wq   = (const float*)d_in[3];
    const float* bq   = (const float*)d_in[4];
    const float* Wk   = (const float*)d_in[5];
    const float* bk   = (const float*)d_in[6];
    const float* Wv   = (const float*)d_in[7];
    const float* bv   = (const float*)d_in[8];
    const float* ln2g = (const float*)d_in[9];
    const float* ln2b = (const float*)d_in[10];
    const float* W1   = (const float*)d_in[11];
    const float* b1   = (const float*)d_in[12];
    const float* W2   = (const float*)d_in[13];
    const float* b2   = (const float*)d_in[14];
    float* out = (float*)d_out;

    float *cc, *part, *partA, *psum, *inv;
    fp16 *S, *Xn, *q, *k, *v, *vt, *ccp, *mid;
    fp16 *Wqp, *Wkp, *Wvp, *W1p, *W2p;
    cudaGetSymbolAddress((void**)&S,    g_S);
    cudaGetSymbolAddress((void**)&psum, g_psum);
    cudaGetSymbolAddress((void**)&inv,  g_inv);
    cudaGetSymbolAddress((void**)&Xn,   g_Xn);
    cudaGetSymbolAddress((void**)&q,    g_q);
    cudaGetSymbolAddress((void**)&k,    g_k);
    cudaGetSymbolAddress((void**)&v,    g_v);
    cudaGetSymbolAddress((void**)&vt,   g_vt);
    cudaGetSymbolAddress((void**)&cc,   g_cc);
    cudaGetSymbolAddress((void**)&ccp,  g_ccp);
    cudaGetSymbolAddress((void**)&mid,  g_mid);
    cudaGetSymbolAddress((void**)&Wqp,  g_Wq);
    cudaGetSymbolAddress((void**)&Wkp,  g_Wk);
    cudaGetSymbolAddress((void**)&Wvp,  g_Wv);
    cudaGetSymbolAddress((void**)&W1p,  g_W1);
    cudaGetSymbolAddress((void**)&W2p,  g_W2);
    cudaGetSymbolAddress((void**)&part, g_part);
    cudaGetSymbolAddress((void**)&partA, g_partA);

    const ZOff z0   = {1, 1, 0, 0};
    const ZOff oQKV = {1, 1, (long)TT * EE, 0};
    const ZOff oS   = {1, 1, (long)TT * TT, 0};
    const ZOff oK1  = {1, 4, 0, 1024};
    const ZOff oP   = {1, 4, 0, (long)BB * TT * EE};

    QKVP qp{};
    qp.w[0] = Wqp; qp.w[1] = Wkp; qp.w[2] = Wvp;
    qp.bias[0] = bq; qp.bias[1] = bk; qp.bias[2] = bv;
    qp.o[0] = q; qp.o[1] = k; qp.o[2] = v;
    QKVP qdummy{};

    const int SMEM = 2 * STAGE_ELEMS * (int)sizeof(fp16);   // 40 KB
    cudaFuncSetAttribute(gemm_h<0, 0>, cudaFuncAttributeMaxDynamicSharedMemorySize, SMEM);
    cudaFuncSetAttribute(gemm_h<0, 3>, cudaFuncAttributeMaxDynamicSharedMemorySize, SMEM);
    cudaFuncSetAttribute(gemm_h<1, 4>, cudaFuncAttributeMaxDynamicSharedMemorySize, SMEM);
    cudaFuncSetAttribute(gemm_h<2, 0>, cudaFuncAttributeMaxDynamicSharedMemorySize, SMEM);
    cudaFuncSetAttribute(gemm_h<3, 1>, cudaFuncAttributeMaxDynamicSharedMemorySize, SMEM);

    dim3 tb(32, 8);

    // 0. one-time weight quantize+transpose
    split_tr<<<dim3(4, 4, HH), tb>>>(Wq, Wqp, EE, EE);
    split_tr<<<dim3(4, 4, HH), tb>>>(Wk, Wkp, EE, EE);
    split_tr<<<dim3(4, 4, HH), tb>>>(Wv, Wvp, EE, EE);
    split_tr<<<dim3(FF / 32, DD / 32, 1), tb>>>(W1, W1p, DD, FF);
    split_tr<<<dim3(EE / 32, FF / 32, 1), tb>>>(W2, W2p, FF, EE);

    // 1. LN1 -> Xn (fp16)
    ln_h<<<BB * TT, 128>>>(X, ln1g, ln1b, Xn, EE);

    // 2. fused QKV projections
    dim3 gqkv(1, TT / 128, 3 * BB * HH);
    gemm_h<1, 4><<<gqkv, 256, SMEM>>>(Xn, nullptr, nullptr, nullptr, nullptr, nullptr,
                                      TT, EE, EE, EE, EE, EE, 1.f, z0, z0, z0, z0, qp);

    // 3. e = exp(Q@K^T/sqrt(E)) with causal zeroing -> fp16 + psums
    dim3 gsc(TT / 128, TT / 128, BB * HH);
    gemm_h<3, 1><<<gsc, 256, SMEM>>>(q, k, nullptr, S, nullptr, psum,
                                     TT, TT, EE, EE, EE, TT,
                                     0.08838834764831845f, oQKV, oQKV, oS, z0, qdummy);

    // 4. column sums -> inv ;  V transpose scaled by inv
    colsum_inv<<<dim3(TT / 256, BB * HH), 256>>>(psum, inv);
    tr_scaled<<<dim3(EE / 32, TT / 32, BB * HH), tb>>>(v, inv, vt, TT, EE);

    // 5. attnV split-K -> partials -> cc
    dim3 gav(1, TT / 128, BB * HH * 4);
    gemm_h<0, 3><<<gav, 256, SMEM>>>(S, vt, partA, nullptr, nullptr, nullptr,
                                     TT, EE, TT, TT, TT, EE, 1.f, z0, z0, z0, z0, qdummy);
    attn_reduce<<<(BB * HH * TT * EE) / 256, 256>>>(partA, cc);

    // 6. LN2 -> ccp (fp16)
    ln_h<<<BB * TT, 256>>>(cc, ln2g, ln2b, ccp, DD);

    // 7. mid = gelu(cc @ W1 + b1)
    dim3 g1(FF / 128, (BB * TT) / 128, 1);
    gemm_h<2, 0><<<g1, 256, SMEM>>>(ccp, W1p, nullptr, mid, b1, nullptr,
                                    BB * TT, FF, DD, DD, DD, FF, 1.f, z0, z0, z0, z0, qdummy);

    // 8. out = mid @ W2 + b2 : split-K x4, then reduce
    dim3 g2(1, (BB * TT) / 128, 4);
    gemm_h<0, 0><<<g2, 256, SMEM>>>(mid, W2p, part, nullptr, nullptr, nullptr,
                                    BB * TT, EE, 1024, FF, FF, EE, 1.f, oK1, oK1, oP, z0, qdummy);
    mlp2_reduce<<<(BB * TT * EE) / 256, 256>>>(part, b2, out);
}